// round 1
// baseline (speedup 1.0000x reference)
#include <cuda_runtime.h>
#include <cstdint>
#include <cstddef>

#define NTHREADS 256
#define BATCH 8192

// ---------------------------------------------------------------------------
// Scratch arena (single __device__ global; regions aliased by lifetime)
// ---------------------------------------------------------------------------
static const size_t OFF_C1    = 0;            // [8192,64,20,20]  209,715,200 f
static const size_t OFF_P1    = 209715200;    // [8192,64,10,10]   52,428,800 f
static const size_t OFF_C2    = 0;            // [8192,128,10,10] 104,857,600 f (c1 dead)
static const size_t OFF_P2    = 209715200;    // [8192,128,5,5]    26,214,400 f (p1 dead)
static const size_t OFF_C3    = 0;            // [8192,256,5,5]    52,428,800 f (c2 dead)
static const size_t OFF_C4    = 52428800;     // [8192,256,5,5]    52,428,800 f
static const size_t OFF_FEATS = 104857600;    // [25,8192,256]     52,428,800 f
static const size_t OFF_H     = 157286400;    // [25,8192,600]    122,880,000 f
static const size_t OFF_PREDS = 280166400;    // [25,8192,10]       2,048,000 f
static const size_t OFF_IN2   = 0;            // [25,8192,336]     68,812,800 f (c3/c4 dead)
static const size_t ARENA_FLOATS = 282214400; // ~1.13 GB

__device__ float g_arena[ARENA_FLOATS];

// ---------------------------------------------------------------------------
// conv1: 3 -> 64, 20x20, pad 1, fused BN+ReLU. One block per image.
// ---------------------------------------------------------------------------
__global__ __launch_bounds__(NTHREADS) void conv1_kernel(
    const float* __restrict__ x, const float* __restrict__ W,
    const float* __restrict__ bias, const float* __restrict__ gam,
    const float* __restrict__ bet, const float* __restrict__ mu,
    const float* __restrict__ var, float* __restrict__ out)
{
    __shared__ float sIn[3 * 22 * 22];   // padded input
    __shared__ float sW[64 * 27];
    __shared__ float sScale[64], sShift[64];
    int b = blockIdx.x, tid = threadIdx.x;

    for (int i = tid; i < 3 * 22 * 22; i += NTHREADS) sIn[i] = 0.f;
    __syncthreads();
    const float* xb = x + (size_t)b * 1200;
    for (int i = tid; i < 1200; i += NTHREADS) {
        int ci = i / 400, p = i % 400, y = p / 20, xx = p % 20;
        sIn[ci * 484 + (y + 1) * 22 + (xx + 1)] = xb[i];
    }
    for (int i = tid; i < 1728; i += NTHREADS) sW[i] = W[i];
    if (tid < 64) {
        float sc = gam[tid] * rsqrtf(var[tid] + 1e-5f);
        sScale[tid] = sc;
        sShift[tid] = (bias[tid] - mu[tid]) * sc + bet[tid];
    }
    __syncthreads();

    int co = tid & 63, q = tid >> 6;   // 4 row-quarters of 5 rows each
    float scale = sScale[co], shift = sShift[co];
    float* ob = out + ((size_t)b * 64 + co) * 400;
    for (int r = 0; r < 5; r++) {
        int y = q * 5 + r;
        float acc[20];
        #pragma unroll
        for (int xx = 0; xx < 20; xx++) acc[xx] = 0.f;
        #pragma unroll
        for (int ci = 0; ci < 3; ci++) {
            float w[9];
            #pragma unroll
            for (int k = 0; k < 9; k++) w[k] = sW[co * 27 + ci * 9 + k];
            const float* base = sIn + ci * 484 + y * 22;
            #pragma unroll
            for (int dy = 0; dy < 3; dy++) {
                const float* row = base + dy * 22;
                #pragma unroll
                for (int xx = 0; xx < 20; xx++)
                    acc[xx] += row[xx] * w[dy * 3] + row[xx + 1] * w[dy * 3 + 1]
                             + row[xx + 2] * w[dy * 3 + 2];
            }
        }
        #pragma unroll
        for (int xx = 0; xx < 20; xx++)
            ob[y * 20 + xx] = fmaxf(acc[xx] * scale + shift, 0.f);
    }
}

// ---------------------------------------------------------------------------
// maxpool 3x3 stride 2 pad 1 (square)
// ---------------------------------------------------------------------------
__global__ __launch_bounds__(NTHREADS) void pool_kernel(
    const float* __restrict__ in, float* __restrict__ out,
    int C, int H, int OH, long long total)
{
    long long idx = (long long)blockIdx.x * NTHREADS + threadIdx.x;
    if (idx >= total) return;
    int W = H, OW = OH;
    int ox = (int)(idx % OW); long long t = idx / OW;
    int oy = (int)(t % OH);  t /= OH;
    int c  = (int)(t % C);   int b = (int)(t / C);
    const float* p = in + ((size_t)b * C + c) * H * W;
    float m = -3.402823466e38f;
    #pragma unroll
    for (int dy = 0; dy < 3; dy++) {
        int iy = 2 * oy - 1 + dy;
        if (iy < 0 || iy >= H) continue;
        #pragma unroll
        for (int dx = 0; dx < 3; dx++) {
            int ix = 2 * ox - 1 + dx;
            if (ix < 0 || ix >= W) continue;
            m = fmaxf(m, p[iy * W + ix]);
        }
    }
    out[idx] = m;
}

// ---------------------------------------------------------------------------
// conv2: 64 -> 128, 10x10, fused BN+ReLU. One block per image.
// Thread = (co, y-half). ci chunked by 8 with weights in shared (stride 73).
// Dynamic smem: sIn 64*144 + sW 128*73  = 74,240 B
// ---------------------------------------------------------------------------
__global__ __launch_bounds__(NTHREADS) void conv2_kernel(
    const float* __restrict__ in, const float* __restrict__ W2,
    const float* __restrict__ bias, const float* __restrict__ gam,
    const float* __restrict__ bet, const float* __restrict__ mu,
    const float* __restrict__ var, float* __restrict__ out)
{
    extern __shared__ float smem[];
    float* sIn = smem;          // 64 * 12 * 12 (padded), zero-filled borders
    float* sW  = smem + 9216;   // 128 * 73
    int b = blockIdx.x, tid = threadIdx.x;

    for (int i = tid; i < 9216; i += NTHREADS) sIn[i] = 0.f;
    __syncthreads();
    const float* ib = in + (size_t)b * 6400;
    for (int i = tid; i < 6400; i += NTHREADS) {
        int ci = i / 100, p = i % 100, y = p / 10, xx = p % 10;
        sIn[ci * 144 + (y + 1) * 12 + xx + 1] = ib[i];
    }

    int co = tid & 127, half = tid >> 7;
    float acc[50];
    #pragma unroll
    for (int i = 0; i < 50; i++) acc[i] = 0.f;

    #pragma unroll 1
    for (int cc = 0; cc < 8; cc++) {
        __syncthreads();   // covers sIn fill (first iter) and prev compute
        for (int i = tid; i < 9216; i += NTHREADS) {
            int c2 = i / 72, j = i % 72;
            sW[c2 * 73 + j] = W2[(size_t)c2 * 576 + cc * 72 + j];
        }
        __syncthreads();
        #pragma unroll 1
        for (int ci8 = 0; ci8 < 8; ci8++) {
            float w[9];
            #pragma unroll
            for (int k = 0; k < 9; k++) w[k] = sW[co * 73 + ci8 * 9 + k];
            const float* pin = sIn + (cc * 8 + ci8) * 144;
            #pragma unroll
            for (int ry = 0; ry < 5; ry++) {
                int y = half * 5 + ry;
                #pragma unroll
                for (int dy = 0; dy < 3; dy++) {
                    const float* row = pin + (y + dy) * 12;
                    #pragma unroll
                    for (int xx = 0; xx < 10; xx++)
                        acc[ry * 10 + xx] += row[xx] * w[dy * 3]
                                           + row[xx + 1] * w[dy * 3 + 1]
                                           + row[xx + 2] * w[dy * 3 + 2];
                }
            }
        }
    }
    float sc = gam[co] * rsqrtf(var[co] + 1e-5f);
    float sh = (bias[co] - mu[co]) * sc + bet[co];
    float* ob = out + ((size_t)b * 128 + co) * 100 + half * 50;
    #pragma unroll
    for (int i = 0; i < 50; i++) ob[i] = fmaxf(acc[i] * sc + sh, 0.f);
}

// ---------------------------------------------------------------------------
// conv3/conv4: CI -> 256, 5x5, fused BN+ReLU. One block per image, thread=co.
// Dynamic smem: CI*49 + 256*73 floats
// ---------------------------------------------------------------------------
template <int CI>
__global__ __launch_bounds__(NTHREADS) void conv5x5_kernel(
    const float* __restrict__ in, const float* __restrict__ W,
    const float* __restrict__ bias, const float* __restrict__ gam,
    const float* __restrict__ bet, const float* __restrict__ mu,
    const float* __restrict__ var, float* __restrict__ out)
{
    extern __shared__ float smem[];
    float* sIn = smem;            // CI * 7 * 7 (padded)
    float* sW  = smem + CI * 49;  // 256 * 73
    int b = blockIdx.x, tid = threadIdx.x;

    for (int i = tid; i < CI * 49; i += NTHREADS) sIn[i] = 0.f;
    __syncthreads();
    const float* ib = in + (size_t)b * CI * 25;
    for (int i = tid; i < CI * 25; i += NTHREADS) {
        int ci = i / 25, p = i % 25;
        sIn[ci * 49 + (p / 5 + 1) * 7 + (p % 5) + 1] = ib[i];
    }

    int co = tid;
    float acc[25];
    #pragma unroll
    for (int i = 0; i < 25; i++) acc[i] = 0.f;

    #pragma unroll 1
    for (int cc = 0; cc < CI / 8; cc++) {
        __syncthreads();
        for (int i = tid; i < 256 * 72; i += NTHREADS) {
            int c2 = i / 72, j = i % 72;
            sW[c2 * 73 + j] = W[(size_t)c2 * (CI * 9) + cc * 72 + j];
        }
        __syncthreads();
        #pragma unroll 1
        for (int ci8 = 0; ci8 < 8; ci8++) {
            float w[9];
            #pragma unroll
            for (int k = 0; k < 9; k++) w[k] = sW[co * 73 + ci8 * 9 + k];
            const float* pin = sIn + (cc * 8 + ci8) * 49;
            #pragma unroll
            for (int y = 0; y < 5; y++)
                #pragma unroll
                for (int dy = 0; dy < 3; dy++) {
                    const float* row = pin + (y + dy) * 7;
                    #pragma unroll
                    for (int xx = 0; xx < 5; xx++)
                        acc[y * 5 + xx] += row[xx] * w[dy * 3]
                                         + row[xx + 1] * w[dy * 3 + 1]
                                         + row[xx + 2] * w[dy * 3 + 2];
                }
        }
    }
    float sc = gam[co] * rsqrtf(var[co] + 1e-5f);
    float sh = (bias[co] - mu[co]) * sc + bet[co];
    float* ob = out + ((size_t)b * 256 + co) * 25;
    #pragma unroll
    for (int i = 0; i < 25; i++) ob[i] = fmaxf(acc[i] * sc + sh, 0.f);
}

// ---------------------------------------------------------------------------
// transpose: feats[n][b][i] = c4[b][i][n]
// ---------------------------------------------------------------------------
__global__ __launch_bounds__(NTHREADS) void transpose_feats_kernel(
    const float* __restrict__ c4, float* __restrict__ feats)
{
    long long idx = (long long)blockIdx.x * NTHREADS + threadIdx.x;
    if (idx >= 25LL * 8192 * 256) return;
    int i = (int)(idx & 255);
    int b = (int)((idx >> 8) & 8191);
    int n = (int)(idx >> 21);
    feats[idx] = c4[((size_t)b * 256 + i) * 25 + n];
}

// ---------------------------------------------------------------------------
// GEMM1: H[n][b][j] = tanh( sum_k A[n][b][k] * Wa[n][k0+k][j] + ba[n][j] )
// 64x64x16 tile, 4x4 register tile, 256 threads. grid (10, 128, 25)
// ---------------------------------------------------------------------------
__global__ __launch_bounds__(NTHREADS) void gemm1_kernel(
    const float* __restrict__ A, const float* __restrict__ Wa,
    const float* __restrict__ ba, float* __restrict__ H, int K, int k0)
{
    __shared__ float sA[16][68];
    __shared__ float sB[16][68];
    int n = blockIdx.z;
    int mBase = blockIdx.y * 64;
    int nBase = blockIdx.x * 64;
    const float* An  = A  + (size_t)n * 8192 * K;
    const float* Wn  = Wa + (size_t)n * 336 * 600;
    const float* ban = ba + (size_t)n * 600;
    int tid = threadIdx.x;
    int ty = tid / 16, tx = tid % 16;
    int la_m = tid / 4, la_k = (tid % 4) * 4;
    int lb_k = tid / 16, lb_n = (tid % 16) * 4;

    float acc[4][4] = {};
    int KT = K / 16;
    for (int kt = 0; kt < KT; kt++) {
        float4 a4 = *(const float4*)&An[(size_t)(mBase + la_m) * K + kt * 16 + la_k];
        sA[la_k + 0][la_m] = a4.x; sA[la_k + 1][la_m] = a4.y;
        sA[la_k + 2][la_m] = a4.z; sA[la_k + 3][la_m] = a4.w;
        int col = nBase + lb_n;
        float4 b4 = make_float4(0.f, 0.f, 0.f, 0.f);
        if (col < 600)
            b4 = *(const float4*)&Wn[(size_t)(k0 + kt * 16 + lb_k) * 600 + col];
        *(float4*)&sB[lb_k][lb_n] = b4;
        __syncthreads();
        #pragma unroll
        for (int kk = 0; kk < 16; kk++) {
            float4 av = *(const float4*)&sA[kk][ty * 4];
            float4 bv = *(const float4*)&sB[kk][tx * 4];
            float ar[4] = {av.x, av.y, av.z, av.w};
            float br[4] = {bv.x, bv.y, bv.z, bv.w};
            #pragma unroll
            for (int i = 0; i < 4; i++)
                #pragma unroll
                for (int j = 0; j < 4; j++)
                    acc[i][j] += ar[i] * br[j];
        }
        __syncthreads();
    }
    #pragma unroll
    for (int i = 0; i < 4; i++) {
        int m = mBase + ty * 4 + i;
        #pragma unroll
        for (int j = 0; j < 4; j++) {
            int c = nBase + tx * 4 + j;
            if (c < 600)
                H[((size_t)n * 8192 + m) * 600 + c] = tanhf(acc[i][j] + ban[c]);
        }
    }
}

// ---------------------------------------------------------------------------
// GEMM2 + softmax: out[n][b][c] = softmax_c( sum_k H[n][b][k]*Wb[n][k][c] + bb )
// Warp per row; Wb in shared with stride-11 pad (conflict-free for k+=32).
// grid (1024, 25), 256 threads.
// ---------------------------------------------------------------------------
__global__ __launch_bounds__(NTHREADS) void gemm2_softmax_kernel(
    const float* __restrict__ H, const float* __restrict__ Wb,
    const float* __restrict__ bb, float* __restrict__ out)
{
    __shared__ float sW[600 * 11];
    __shared__ float sb[10];
    int n = blockIdx.y, tid = threadIdx.x;
    const float* Wn = Wb + (size_t)n * 6000;
    for (int i = tid; i < 6000; i += NTHREADS) {
        int k = i / 10, c = i % 10;
        sW[k * 11 + c] = Wn[i];
    }
    if (tid < 10) sb[tid] = bb[n * 10 + tid];
    __syncthreads();

    int warp = tid >> 5, lane = tid & 31;
    int b = blockIdx.x * 8 + warp;
    const float* hr = H + ((size_t)n * 8192 + b) * 600;
    float acc[10];
    #pragma unroll
    for (int c = 0; c < 10; c++) acc[c] = 0.f;
    for (int k = lane; k < 600; k += 32) {
        float v = hr[k];
        #pragma unroll
        for (int c = 0; c < 10; c++) acc[c] += v * sW[k * 11 + c];
    }
    #pragma unroll
    for (int c = 0; c < 10; c++) {
        #pragma unroll
        for (int off = 16; off > 0; off >>= 1)
            acc[c] += __shfl_down_sync(0xffffffffu, acc[c], off);
    }
    if (lane == 0) {
        float l[10], mx = -3.402823466e38f;
        #pragma unroll
        for (int c = 0; c < 10; c++) { l[c] = acc[c] + sb[c]; mx = fmaxf(mx, l[c]); }
        float s = 0.f;
        #pragma unroll
        for (int c = 0; c < 10; c++) { l[c] = expf(l[c] - mx); s += l[c]; }
        float inv = 1.f / s;
        float* o = out + ((size_t)n * 8192 + b) * 10;
        #pragma unroll
        for (int c = 0; c < 10; c++) o[c] = l[c] * inv;
    }
}

// ---------------------------------------------------------------------------
// neighbor table (matches reference Brain.neighbors ordering, 5x5 grid)
// ---------------------------------------------------------------------------
__device__ __forceinline__ int nei_of(int i, int slot)
{
    int nb[8];
    #pragma unroll
    for (int t = 0; t < 8; t++) nb[t] = -1;
    int cnt = 0;
    bool l = (i % 5 != 0), r = ((i + 1) % 5 != 0), u = (i >= 5), d = (i + 5 < 25);
    if (u)      nb[cnt++] = i - 5;
    if (l)      nb[cnt++] = i - 1;
    if (r)      nb[cnt++] = i + 1;
    if (d)      nb[cnt++] = i + 5;
    if (u && l) nb[cnt++] = i - 6;
    if (u && r) nb[cnt++] = i - 4;
    if (d && l) nb[cnt++] = i + 4;
    if (d && r) nb[cnt++] = i + 6;
    return nb[slot];
}

// in2[n][b][0:80] = masked neighbor preds, [80:336] = feats
__global__ __launch_bounds__(NTHREADS) void gather_kernel(
    const float* __restrict__ preds, const float* __restrict__ feats,
    float* __restrict__ in2)
{
    long long idx = (long long)blockIdx.x * NTHREADS + threadIdx.x;
    if (idx >= 25LL * 8192 * 336) return;
    int j = (int)(idx % 336);
    long long t = idx / 336;
    int b = (int)(t % 8192);
    int n = (int)(t / 8192);
    float v;
    if (j >= 80) {
        v = feats[((size_t)n * 8192 + b) * 256 + (j - 80)];
    } else {
        int s = j / 10, c = j % 10;
        int nei = nei_of(n, s);
        v = (nei >= 0) ? preds[((size_t)nei * 8192 + b) * 10 + c] : 0.f;
    }
    in2[idx] = v;
}

// mean over 25 nodes
__global__ __launch_bounds__(NTHREADS) void mean_kernel(
    const float* __restrict__ second, float* __restrict__ mean)
{
    int idx = blockIdx.x * NTHREADS + threadIdx.x;
    if (idx >= 81920) return;
    float s = 0.f;
    #pragma unroll
    for (int n = 0; n < 25; n++) s += second[(size_t)n * 81920 + idx];
    mean[idx] = s * 0.04f;
}

// ---------------------------------------------------------------------------
// launch
// ---------------------------------------------------------------------------
extern "C" void kernel_launch(void* const* d_in, const int* in_sizes, int n_in,
                              void* d_out, int out_size)
{
    (void)in_sizes; (void)n_in; (void)out_size;
    float* arena = nullptr;
    cudaGetSymbolAddress((void**)&arena, g_arena);

    const float* x   = (const float*)d_in[0];
    const float* W1  = (const float*)d_in[1];
    const float* b1  = (const float*)d_in[2];
    const float* g1  = (const float*)d_in[3];
    const float* be1 = (const float*)d_in[4];
    const float* m1  = (const float*)d_in[5];
    const float* v1  = (const float*)d_in[6];
    const float* W2  = (const float*)d_in[7];
    const float* b2  = (const float*)d_in[8];
    const float* g2  = (const float*)d_in[9];
    const float* be2 = (const float*)d_in[10];
    const float* m2  = (const float*)d_in[11];
    const float* v2  = (const float*)d_in[12];
    const float* W3  = (const float*)d_in[13];
    const float* b3  = (const float*)d_in[14];
    const float* g3  = (const float*)d_in[15];
    const float* be3 = (const float*)d_in[16];
    const float* m3  = (const float*)d_in[17];
    const float* v3  = (const float*)d_in[18];
    const float* W4  = (const float*)d_in[19];
    const float* b4  = (const float*)d_in[20];
    const float* g4  = (const float*)d_in[21];
    const float* be4 = (const float*)d_in[22];
    const float* m4  = (const float*)d_in[23];
    const float* v4  = (const float*)d_in[24];
    const float* Wa  = (const float*)d_in[25];
    const float* ba  = (const float*)d_in[26];
    const float* Wb  = (const float*)d_in[27];
    const float* bb  = (const float*)d_in[28];
    float* out = (float*)d_out;

    const int SMEM2 = (9216 + 128 * 73) * 4;          //  74,240 B
    const int SMEM3 = (128 * 49 + 256 * 73) * 4;      //  99,840 B
    const int SMEM4 = (256 * 49 + 256 * 73) * 4;      // 124,928 B
    cudaFuncSetAttribute(conv2_kernel, cudaFuncAttributeMaxDynamicSharedMemorySize, SMEM2);
    cudaFuncSetAttribute(conv5x5_kernel<128>, cudaFuncAttributeMaxDynamicSharedMemorySize, SMEM3);
    cudaFuncSetAttribute(conv5x5_kernel<256>, cudaFuncAttributeMaxDynamicSharedMemorySize, SMEM4);

    // conv1 + pool1
    conv1_kernel<<<BATCH, NTHREADS>>>(x, W1, b1, g1, be1, m1, v1, arena + OFF_C1);
    {
        long long total = (long long)BATCH * 64 * 100;
        pool_kernel<<<(int)((total + NTHREADS - 1) / NTHREADS), NTHREADS>>>(
            arena + OFF_C1, arena + OFF_P1, 64, 20, 10, total);
    }
    // conv2 + pool2
    conv2_kernel<<<BATCH, NTHREADS, SMEM2>>>(arena + OFF_P1, W2, b2, g2, be2, m2, v2,
                                             arena + OFF_C2);
    {
        long long total = (long long)BATCH * 128 * 25;
        pool_kernel<<<(int)((total + NTHREADS - 1) / NTHREADS), NTHREADS>>>(
            arena + OFF_C2, arena + OFF_P2, 128, 10, 5, total);
    }
    // conv3, conv4
    conv5x5_kernel<128><<<BATCH, NTHREADS, SMEM3>>>(arena + OFF_P2, W3, b3, g3, be3, m3, v3,
                                                    arena + OFF_C3);
    conv5x5_kernel<256><<<BATCH, NTHREADS, SMEM4>>>(arena + OFF_C3, W4, b4, g4, be4, m4, v4,
                                                    arena + OFF_C4);
    // feats
    {
        long long total = 25LL * 8192 * 256;
        transpose_feats_kernel<<<(int)((total + NTHREADS - 1) / NTHREADS), NTHREADS>>>(
            arena + OFF_C4, arena + OFF_FEATS);
    }
    // stage 1 MLP (first 80 inputs are zeros -> use Wa rows 80:336)
    gemm1_kernel<<<dim3(10, 128, 25), NTHREADS>>>(arena + OFF_FEATS, Wa, ba,
                                                  arena + OFF_H, 256, 80);
    gemm2_softmax_kernel<<<dim3(1024, 25), NTHREADS>>>(arena + OFF_H, Wb, bb,
                                                       arena + OFF_PREDS);
    // neighbor gather + concat
    {
        long long total = 25LL * 8192 * 336;
        gather_kernel<<<(int)((total + NTHREADS - 1) / NTHREADS), NTHREADS>>>(
            arena + OFF_PREDS, arena + OFF_FEATS, arena + OFF_IN2);
    }
    // stage 2 MLP -> second written straight into d_out[81920:]
    gemm1_kernel<<<dim3(10, 128, 25), NTHREADS>>>(arena + OFF_IN2, Wa, ba,
                                                  arena + OFF_H, 336, 0);
    gemm2_softmax_kernel<<<dim3(1024, 25), NTHREADS>>>(arena + OFF_H, Wb, bb,
                                                       out + 81920);
    // mean over nodes -> d_out[0:81920]
    mean_kernel<<<320, NTHREADS>>>(out + 81920, out);
}

// round 4
// speedup vs baseline: 1.5979x; 1.5979x over previous
#include <cuda_runtime.h>
#include <cstdint>
#include <cstddef>

#define NTHREADS 256
#define BATCH 8192

// ---------------------------------------------------------------------------
// Scratch (single __device__ global arena; regions aliased by lifetime)
//  c1   [0, 209715200)                 conv1 out [b][64][20][20]
//  p1   [209715200, 262144000)         pool1 out [b][64][10][10]
//  c2   [0, 104857600)                 conv2 out [b][128][10][10]   (c1 dead)
//  p2   [104857600, 131072000)         pool2 out [b][128][5][5]
//  c3   [131072000, 183500800)         conv3 out [b][256][5][5]
//  feats[0, 52428800)                  [25][8192][256]              (c2 dead)
//  H    [52428800, 175308800)          [25][8192][600]              (p2/c3 dead)
//  preds[175308800, 177356800)         [25][8192][10]
//  in2  [177356800, 246169600)         [25][8192][336]              (p1 dead)
// ---------------------------------------------------------------------------
__device__ float g_arena[262144000];     // 1.049 GB total statics

static const size_t OFF_C1    = 0;
static const size_t OFF_P1    = 209715200;
static const size_t OFF_C2    = 0;
static const size_t OFF_P2    = 104857600;
static const size_t OFF_C3    = 131072000;
static const size_t OFF_FEATS = 0;
static const size_t OFF_H     = 52428800;
static const size_t OFF_PREDS = 175308800;
static const size_t OFF_IN2   = 177356800;

// transposed weights [K][N] + folded BN scale/shift
__device__ float g_w2t[576 * 128];
__device__ float g_w3t[1152 * 256];
__device__ float g_w4t[2304 * 256];
__device__ float g_sc2[128], g_sh2[128];
__device__ float g_sc3[256], g_sh3[256];
__device__ float g_sc4[256], g_sh4[256];

// ---------------------------------------------------------------------------
// tf32 helpers
// ---------------------------------------------------------------------------
__device__ __forceinline__ void tf32split(float x, uint32_t& hi, uint32_t& lo)
{
    uint32_t h;
    asm("cvt.rna.tf32.f32 %0, %1;" : "=r"(h) : "f"(x));
    float r = x - __uint_as_float(h);
    uint32_t l;
    asm("cvt.rna.tf32.f32 %0, %1;" : "=r"(l) : "f"(r));
    hi = h; lo = l;
}

__device__ __forceinline__ void mma8(float d[4], const uint32_t a[4], const uint32_t b[2])
{
    asm volatile(
        "mma.sync.aligned.m16n8k8.row.col.f32.tf32.tf32.f32 "
        "{%0,%1,%2,%3}, {%4,%5,%6,%7}, {%8,%9}, {%0,%1,%2,%3};\n"
        : "+f"(d[0]), "+f"(d[1]), "+f"(d[2]), "+f"(d[3])
        : "r"(a[0]), "r"(a[1]), "r"(a[2]), "r"(a[3]), "r"(b[0]), "r"(b[1]));
}

// ---------------------------------------------------------------------------
// prep: weight transposes + BN fold
// ---------------------------------------------------------------------------
__global__ __launch_bounds__(NTHREADS) void prep_kernel(
    const float* __restrict__ W2, const float* __restrict__ W3, const float* __restrict__ W4,
    const float* __restrict__ b2, const float* __restrict__ g2, const float* __restrict__ be2,
    const float* __restrict__ m2, const float* __restrict__ v2,
    const float* __restrict__ b3, const float* __restrict__ g3, const float* __restrict__ be3,
    const float* __restrict__ m3, const float* __restrict__ v3,
    const float* __restrict__ b4, const float* __restrict__ g4, const float* __restrict__ be4,
    const float* __restrict__ m4, const float* __restrict__ v4)
{
    int idx = blockIdx.x * NTHREADS + threadIdx.x;
    if (idx < 576 * 128) {
        int k = idx >> 7, n = idx & 127;
        g_w2t[idx] = W2[n * 576 + k];
    }
    int i3 = idx - 73728;
    if (i3 >= 0 && i3 < 1152 * 256) {
        int k = i3 >> 8, n = i3 & 255;
        g_w3t[i3] = W3[n * 1152 + k];
    }
    int i4 = idx - 73728 - 294912;
    if (i4 >= 0 && i4 < 2304 * 256) {
        int k = i4 >> 8, n = i4 & 255;
        g_w4t[i4] = W4[n * 2304 + k];
    }
    if (idx < 128) {
        float s = g2[idx] * rsqrtf(v2[idx] + 1e-5f);
        g_sc2[idx] = s; g_sh2[idx] = (b2[idx] - m2[idx]) * s + be2[idx];
    } else if (idx < 384) {
        int c = idx - 128;
        float s = g3[c] * rsqrtf(v3[c] + 1e-5f);
        g_sc3[c] = s; g_sh3[c] = (b3[c] - m3[c]) * s + be3[c];
    } else if (idx < 640) {
        int c = idx - 384;
        float s = g4[c] * rsqrtf(v4[c] + 1e-5f);
        g_sc4[c] = s; g_sh4[c] = (b4[c] - m4[c]) * s + be4[c];
    }
}

// ---------------------------------------------------------------------------
// conv1: 3 -> 64, 20x20, fused BN+ReLU. One block per image. (small: FFMA ok)
// ---------------------------------------------------------------------------
__global__ __launch_bounds__(NTHREADS) void conv1_kernel(
    const float* __restrict__ x, const float* __restrict__ W,
    const float* __restrict__ bias, const float* __restrict__ gam,
    const float* __restrict__ bet, const float* __restrict__ mu,
    const float* __restrict__ var, float* __restrict__ out)
{
    __shared__ float sIn[3 * 22 * 22];
    __shared__ float sW[64 * 27];
    __shared__ float sScale[64], sShift[64];
    int b = blockIdx.x, tid = threadIdx.x;

    for (int i = tid; i < 3 * 22 * 22; i += NTHREADS) sIn[i] = 0.f;
    __syncthreads();
    const float* xb = x + (size_t)b * 1200;
    for (int i = tid; i < 1200; i += NTHREADS) {
        int ci = i / 400, p = i % 400, y = p / 20, xx = p % 20;
        sIn[ci * 484 + (y + 1) * 22 + (xx + 1)] = xb[i];
    }
    for (int i = tid; i < 1728; i += NTHREADS) sW[i] = W[i];
    if (tid < 64) {
        float sc = gam[tid] * rsqrtf(var[tid] + 1e-5f);
        sScale[tid] = sc;
        sShift[tid] = (bias[tid] - mu[tid]) * sc + bet[tid];
    }
    __syncthreads();

    int co = tid & 63, q = tid >> 6;
    float scale = sScale[co], shift = sShift[co];
    float* ob = out + ((size_t)b * 64 + co) * 400;
    for (int r = 0; r < 5; r++) {
        int y = q * 5 + r;
        float acc[20];
        #pragma unroll
        for (int xx = 0; xx < 20; xx++) acc[xx] = 0.f;
        #pragma unroll
        for (int ci = 0; ci < 3; ci++) {
            float w[9];
            #pragma unroll
            for (int k = 0; k < 9; k++) w[k] = sW[co * 27 + ci * 9 + k];
            const float* base = sIn + ci * 484 + y * 22;
            #pragma unroll
            for (int dy = 0; dy < 3; dy++) {
                const float* row = base + dy * 22;
                #pragma unroll
                for (int xx = 0; xx < 20; xx++)
                    acc[xx] += row[xx] * w[dy * 3] + row[xx + 1] * w[dy * 3 + 1]
                             + row[xx + 2] * w[dy * 3 + 2];
            }
        }
        #pragma unroll
        for (int xx = 0; xx < 20; xx++)
            ob[y * 20 + xx] = fmaxf(acc[xx] * scale + shift, 0.f);
    }
}

// ---------------------------------------------------------------------------
// maxpool 3x3 stride 2 pad 1
// ---------------------------------------------------------------------------
__global__ __launch_bounds__(NTHREADS) void pool_kernel(
    const float* __restrict__ in, float* __restrict__ out,
    int C, int H, int OH, long long total)
{
    long long idx = (long long)blockIdx.x * NTHREADS + threadIdx.x;
    if (idx >= total) return;
    int W = H, OW = OH;
    int ox = (int)(idx % OW); long long t = idx / OW;
    int oy = (int)(t % OH);  t /= OH;
    int c  = (int)(t % C);   int b = (int)(t / C);
    const float* p = in + ((size_t)b * C + c) * H * W;
    float m = -3.402823466e38f;
    #pragma unroll
    for (int dy = 0; dy < 3; dy++) {
        int iy = 2 * oy - 1 + dy;
        if (iy < 0 || iy >= H) continue;
        #pragma unroll
        for (int dx = 0; dx < 3; dx++) {
            int ix = 2 * ox - 1 + dx;
            if (ix < 0 || ix >= W) continue;
            m = fmaxf(m, p[iy * W + ix]);
        }
    }
    out[idx] = m;
}

// ---------------------------------------------------------------------------
// Tensor-core GEMM with IMPLICIT im2col on the A side.
// C[M,N] = A[M,K] x Bt[K,N], 3xTF32 (fp32-accurate).
// Tile 128x128x16, 256 threads (8 warps as 4x2), m16n8k8 fragments.
// CC > 0: A row r=(b,p) over input [b][CC][S][S]; k=(ci,q), 3x3 pad-1 taps.
// CC == 0: dense A load (MLP), row-major A[M][K].
// EPI: 0 conv2 store [b][128][100], 1 conv3 store [b][256][25],
//      2 conv4 -> feats[p][b][256], 3 MLP tanh -> H[z][8192][600]
// ---------------------------------------------------------------------------
template <int EPI, int CC, int S>
__global__ __launch_bounds__(NTHREADS) void gemm_tc(
    const float* __restrict__ A, const float* __restrict__ Bt,
    float* __restrict__ C, const float* __restrict__ sc,
    const float* __restrict__ sh, const float* __restrict__ bias,
    int K, int N, int ldb)
{
    __shared__ float sA[16 * 136];
    __shared__ float sB[16 * 136];

    int z = blockIdx.z;
    const float* Ab = A;
    const float* Bb = Bt;
    if (EPI == 3) {
        Ab += (size_t)z * 8192 * K;
        Bb += (size_t)z * 336 * 600;
    }
    int mBase = blockIdx.y * 128, nBase = blockIdx.x * 128;
    int t = threadIdx.x;
    int lane = t & 31, wid = t >> 5;
    int wm = (wid & 3) * 32, wn = (wid >> 2) * 64;
    int lc = lane & 3, lr = lane >> 2;

    // implicit-im2col per-thread row decode (2 rows per thread: m = t>>1 pairs)
    // load mapping: idx = t*2+i -> m = idx>>2, kq = (idx&3)*4
    float acc[2][8][4];
    #pragma unroll
    for (int mt = 0; mt < 2; mt++)
        #pragma unroll
        for (int nt = 0; nt < 8; nt++)
            #pragma unroll
            for (int e = 0; e < 4; e++) acc[mt][nt][e] = 0.f;

    for (int kc = 0; kc < K; kc += 16) {
        __syncthreads();
        // ---- load A chunk (128 x 16) -> sA[k][m]
        #pragma unroll
        for (int i = 0; i < 2; i++) {
            int idx = t * 2 + i;
            int m = idx >> 2, kq = (idx & 3) * 4;
            if (CC == 0) {
                float4 v = *(const float4*)(Ab + (size_t)(mBase + m) * K + kc + kq);
                sA[(kq + 0) * 136 + m] = v.x;
                sA[(kq + 1) * 136 + m] = v.y;
                sA[(kq + 2) * 136 + m] = v.z;
                sA[(kq + 3) * 136 + m] = v.w;
            } else {
                const int SS = S * S;
                int r = mBase + m;
                int b = r / SS, p = r - b * SS;
                int py = p / S, px = p - py * S;
                const float* ib = Ab + (size_t)b * CC * SS;
                #pragma unroll
                for (int j = 0; j < 4; j++) {
                    int k = kc + kq + j;
                    int ci = k / 9, q = k - ci * 9;
                    int iy = py - 1 + q / 3, ix = px - 1 + q % 3;
                    float v = 0.f;
                    if (iy >= 0 && iy < S && ix >= 0 && ix < S)
                        v = ib[ci * SS + iy * S + ix];
                    sA[(kq + j) * 136 + m] = v;
                }
            }
        }
        // ---- load B chunk (16 x 128) -> sB[k][n]
        #pragma unroll
        for (int i = 0; i < 2; i++) {
            int idx = t * 2 + i;
            int kr = idx >> 5, nq = (idx & 31) * 4;
            int gn = nBase + nq;
            float4 v = make_float4(0.f, 0.f, 0.f, 0.f);
            if (gn < N) v = *(const float4*)(Bb + (size_t)(kc + kr) * ldb + gn);
            *(float4*)&sB[kr * 136 + nq] = v;
        }
        __syncthreads();

        #pragma unroll
        for (int kk = 0; kk < 16; kk += 8) {
            uint32_t ah[2][4], al[2][4];
            #pragma unroll
            for (int mt = 0; mt < 2; mt++) {
                int mr = wm + mt * 16 + lr;
                float x0 = sA[(kk + lc) * 136 + mr];
                float x1 = sA[(kk + lc) * 136 + mr + 8];
                float x2 = sA[(kk + lc + 4) * 136 + mr];
                float x3 = sA[(kk + lc + 4) * 136 + mr + 8];
                tf32split(x0, ah[mt][0], al[mt][0]);
                tf32split(x1, ah[mt][1], al[mt][1]);
                tf32split(x2, ah[mt][2], al[mt][2]);
                tf32split(x3, ah[mt][3], al[mt][3]);
            }
            #pragma unroll
            for (int nt = 0; nt < 8; nt++) {
                int nc = wn + nt * 8 + lr;
                float y0 = sB[(kk + lc) * 136 + nc];
                float y1 = sB[(kk + lc + 4) * 136 + nc];
                uint32_t bh[2], bl[2];
                tf32split(y0, bh[0], bl[0]);
                tf32split(y1, bh[1], bl[1]);
                #pragma unroll
                for (int mt = 0; mt < 2; mt++) {
                    mma8(acc[mt][nt], ah[mt], bh);
                    mma8(acc[mt][nt], al[mt], bh);
                    mma8(acc[mt][nt], ah[mt], bl);
                }
            }
        }
    }

    // epilogue
    #pragma unroll
    for (int mt = 0; mt < 2; mt++) {
        #pragma unroll
        for (int nt = 0; nt < 8; nt++) {
            #pragma unroll
            for (int e = 0; e < 4; e++) {
                int row = mBase + wm + mt * 16 + lr + (e >> 1) * 8;
                int col = nBase + wn + nt * 8 + 2 * lc + (e & 1);
                float v = acc[mt][nt][e];
                if (EPI == 0) {
                    int b = row / 100, p = row - b * 100;
                    C[((size_t)b * 128 + col) * 100 + p] = fmaxf(v * sc[col] + sh[col], 0.f);
                } else if (EPI == 1) {
                    int b = row / 25, p = row - b * 25;
                    C[((size_t)b * 256 + col) * 25 + p] = fmaxf(v * sc[col] + sh[col], 0.f);
                } else if (EPI == 2) {
                    int b = row / 25, p = row - b * 25;
                    C[((size_t)p * 8192 + b) * 256 + col] = fmaxf(v * sc[col] + sh[col], 0.f);
                } else {
                    if (col < N)
                        C[((size_t)z * 8192 + row) * 600 + col] =
                            tanhf(v + bias[(size_t)z * 600 + col]);
                }
            }
        }
    }
}

// ---------------------------------------------------------------------------
// GEMM2 + softmax (600 -> 10), warp per row, Wb in smem (pad 11)
// ---------------------------------------------------------------------------
__global__ __launch_bounds__(NTHREADS) void gemm2_softmax_kernel(
    const float* __restrict__ H, const float* __restrict__ Wb,
    const float* __restrict__ bb, float* __restrict__ out)
{
    __shared__ float sW[600 * 11];
    __shared__ float sb[10];
    int n = blockIdx.y, tid = threadIdx.x;
    const float* Wn = Wb + (size_t)n * 6000;
    for (int i = tid; i < 6000; i += NTHREADS) {
        int k = i / 10, c = i % 10;
        sW[k * 11 + c] = Wn[i];
    }
    if (tid < 10) sb[tid] = bb[n * 10 + tid];
    __syncthreads();

    int warp = tid >> 5, lane = tid & 31;
    int b = blockIdx.x * 8 + warp;
    const float* hr = H + ((size_t)n * 8192 + b) * 600;
    float acc[10];
    #pragma unroll
    for (int c = 0; c < 10; c++) acc[c] = 0.f;
    for (int k = lane; k < 600; k += 32) {
        float v = hr[k];
        #pragma unroll
        for (int c = 0; c < 10; c++) acc[c] += v * sW[k * 11 + c];
    }
    #pragma unroll
    for (int c = 0; c < 10; c++) {
        #pragma unroll
        for (int off = 16; off > 0; off >>= 1)
            acc[c] += __shfl_down_sync(0xffffffffu, acc[c], off);
    }
    if (lane == 0) {
        float l[10], mx = -3.402823466e38f;
        #pragma unroll
        for (int c = 0; c < 10; c++) { l[c] = acc[c] + sb[c]; mx = fmaxf(mx, l[c]); }
        float s = 0.f;
        #pragma unroll
        for (int c = 0; c < 10; c++) { l[c] = expf(l[c] - mx); s += l[c]; }
        float inv = 1.f / s;
        float* o = out + ((size_t)n * 8192 + b) * 10;
        #pragma unroll
        for (int c = 0; c < 10; c++) o[c] = l[c] * inv;
    }
}

// ---------------------------------------------------------------------------
// neighbor gather (matches reference Brain.neighbors ordering, 5x5 grid)
// ---------------------------------------------------------------------------
__device__ __forceinline__ int nei_of(int i, int slot)
{
    int nb[8];
    #pragma unroll
    for (int t = 0; t < 8; t++) nb[t] = -1;
    int cnt = 0;
    bool l = (i % 5 != 0), r = ((i + 1) % 5 != 0), u = (i >= 5), d = (i + 5 < 25);
    if (u)      nb[cnt++] = i - 5;
    if (l)      nb[cnt++] = i - 1;
    if (r)      nb[cnt++] = i + 1;
    if (d)      nb[cnt++] = i + 5;
    if (u && l) nb[cnt++] = i - 6;
    if (u && r) nb[cnt++] = i - 4;
    if (d && l) nb[cnt++] = i + 4;
    if (d && r) nb[cnt++] = i + 6;
    return nb[slot];
}

__global__ __launch_bounds__(NTHREADS) void gather_kernel(
    const float* __restrict__ preds, const float* __restrict__ feats,
    float* __restrict__ in2)
{
    long long idx = (long long)blockIdx.x * NTHREADS + threadIdx.x;
    if (idx >= 25LL * 8192 * 336) return;
    int j = (int)(idx % 336);
    long long t = idx / 336;
    int b = (int)(t % 8192);
    int n = (int)(t / 8192);
    float v;
    if (j >= 80) {
        v = feats[((size_t)n * 8192 + b) * 256 + (j - 80)];
    } else {
        int s = j / 10, c = j % 10;
        int nei = nei_of(n, s);
        v = (nei >= 0) ? preds[((size_t)nei * 8192 + b) * 10 + c] : 0.f;
    }
    in2[idx] = v;
}

__global__ __launch_bounds__(NTHREADS) void mean_kernel(
    const float* __restrict__ second, float* __restrict__ mean)
{
    int idx = blockIdx.x * NTHREADS + threadIdx.x;
    if (idx >= 81920) return;
    float s = 0.f;
    #pragma unroll
    for (int n = 0; n < 25; n++) s += second[(size_t)n * 81920 + idx];
    mean[idx] = s * 0.04f;
}

// ---------------------------------------------------------------------------
// launch
// ---------------------------------------------------------------------------
extern "C" void kernel_launch(void* const* d_in, const int* in_sizes, int n_in,
                              void* d_out, int out_size)
{
    (void)in_sizes; (void)n_in; (void)out_size;
    float *arena = nullptr;
    float *w2t, *w3t, *w4t, *sc2, *sh2, *sc3, *sh3, *sc4, *sh4;
    cudaGetSymbolAddress((void**)&arena, g_arena);
    cudaGetSymbolAddress((void**)&w2t, g_w2t);
    cudaGetSymbolAddress((void**)&w3t, g_w3t);
    cudaGetSymbolAddress((void**)&w4t, g_w4t);
    cudaGetSymbolAddress((void**)&sc2, g_sc2);
    cudaGetSymbolAddress((void**)&sh2, g_sh2);
    cudaGetSymbolAddress((void**)&sc3, g_sc3);
    cudaGetSymbolAddress((void**)&sh3, g_sh3);
    cudaGetSymbolAddress((void**)&sc4, g_sc4);
    cudaGetSymbolAddress((void**)&sh4, g_sh4);

    const float* x   = (const float*)d_in[0];
    const float* W1  = (const float*)d_in[1];
    const float* b1  = (const float*)d_in[2];
    const float* g1  = (const float*)d_in[3];
    const float* be1 = (const float*)d_in[4];
    const float* m1  = (const float*)d_in[5];
    const float* v1  = (const float*)d_in[6];
    const float* W2  = (const float*)d_in[7];
    const float* b2  = (const float*)d_in[8];
    const float* g2  = (const float*)d_in[9];
    const float* be2 = (const float*)d_in[10];
    const float* m2  = (const float*)d_in[11];
    const float* v2  = (const float*)d_in[12];
    const float* W3  = (const float*)d_in[13];
    const float* b3  = (const float*)d_in[14];
    const float* g3  = (const float*)d_in[15];
    const float* be3 = (const float*)d_in[16];
    const float* m3  = (const float*)d_in[17];
    const float* v3  = (const float*)d_in[18];
    const float* W4  = (const float*)d_in[19];
    const float* b4  = (const float*)d_in[20];
    const float* g4  = (const float*)d_in[21];
    const float* be4 = (const float*)d_in[22];
    const float* m4  = (const float*)d_in[23];
    const float* v4  = (const float*)d_in[24];
    const float* Wa  = (const float*)d_in[25];
    const float* ba  = (const float*)d_in[26];
    const float* Wb  = (const float*)d_in[27];
    const float* bb  = (const float*)d_in[28];
    float* out = (float*)d_out;

    // prep (weight transposes + BN folds)
    prep_kernel<<<3744, NTHREADS>>>(W2, W3, W4,
        b2, g2, be2, m2, v2, b3, g3, be3, m3, v3, b4, g4, be4, m4, v4);

    // conv1 + pool1
    conv1_kernel<<<BATCH, NTHREADS>>>(x, W1, b1, g1, be1, m1, v1, arena + OFF_C1);
    {
        long long total = (long long)BATCH * 64 * 100;
        pool_kernel<<<(int)((total + NTHREADS - 1) / NTHREADS), NTHREADS>>>(
            arena + OFF_C1, arena + OFF_P1, 64, 20, 10, total);
    }
    // conv2: implicit-im2col GEMM over pool1 (K=576, N=128)
    gemm_tc<0, 64, 10><<<dim3(1, 6400, 1), NTHREADS>>>(
        arena + OFF_P1, w2t, arena + OFF_C2, sc2, sh2, nullptr, 576, 128, 128);
    // pool2
    {
        long long total = (long long)BATCH * 128 * 25;
        pool_kernel<<<(int)((total + NTHREADS - 1) / NTHREADS), NTHREADS>>>(
            arena + OFF_C2, arena + OFF_P2, 128, 10, 5, total);
    }
    // conv3: implicit-im2col GEMM over pool2 (K=1152, N=256)
    gemm_tc<1, 128, 5><<<dim3(2, 1600, 1), NTHREADS>>>(
        arena + OFF_P2, w3t, arena + OFF_C3, sc3, sh3, nullptr, 1152, 256, 256);
    // conv4: implicit-im2col GEMM over c3, writes feats[n][b][c] directly (K=2304)
    gemm_tc<2, 256, 5><<<dim3(2, 1600, 1), NTHREADS>>>(
        arena + OFF_C3, w4t, arena + OFF_FEATS, sc4, sh4, nullptr, 2304, 256, 256);
    // stage 1 MLP (first 80 inputs zero -> Wa rows 80:336, K=256)
    gemm_tc<3, 0, 0><<<dim3(5, 64, 25), NTHREADS>>>(
        arena + OFF_FEATS, Wa + 80 * 600, arena + OFF_H, nullptr, nullptr, ba,
        256, 600, 600);
    gemm2_softmax_kernel<<<dim3(1024, 25), NTHREADS>>>(arena + OFF_H, Wb, bb,
                                                       arena + OFF_PREDS);
    // neighbor gather
    {
        long long total = 25LL * 8192 * 336;
        gather_kernel<<<(int)((total + NTHREADS - 1) / NTHREADS), NTHREADS>>>(
            arena + OFF_PREDS, arena + OFF_FEATS, arena + OFF_IN2);
    }
    // stage 2 MLP (K=336)
    gemm_tc<3, 0, 0><<<dim3(5, 64, 25), NTHREADS>>>(
        arena + OFF_IN2, Wa, arena + OFF_H, nullptr, nullptr, ba,
        336, 600, 600);
    gemm2_softmax_kernel<<<dim3(1024, 25), NTHREADS>>>(arena + OFF_H, Wb, bb,
                                                       out + 81920);
    mean_kernel<<<320, NTHREADS>>>(out + 81920, out);
}

// round 5
// speedup vs baseline: 1.6302x; 1.0202x over previous
#include <cuda_runtime.h>
#include <cstdint>
#include <cstddef>

#define NTHREADS 256
#define BATCH 8192

// ---------------------------------------------------------------------------
// Scratch (single __device__ global arena; regions aliased by lifetime)
// ---------------------------------------------------------------------------
__device__ float g_arena[262144000];     // 1.049 GB total statics

static const size_t OFF_C1    = 0;
static const size_t OFF_P1    = 209715200;
static const size_t OFF_C2    = 0;
static const size_t OFF_P2    = 104857600;
static const size_t OFF_C3    = 131072000;
static const size_t OFF_FEATS = 0;
static const size_t OFF_H     = 52428800;
static const size_t OFF_PREDS = 175308800;
static const size_t OFF_IN2   = 177356800;

// transposed weights [K][N] + folded BN scale/shift
__device__ float g_w2t[576 * 128];
__device__ float g_w3t[1152 * 256];
__device__ float g_w4t[2304 * 256];
__device__ float g_sc2[128], g_sh2[128];
__device__ float g_sc3[256], g_sh3[256];
__device__ float g_sc4[256], g_sh4[256];

// ---------------------------------------------------------------------------
// tf32 helpers
// ---------------------------------------------------------------------------
__device__ __forceinline__ uint2 tf32split2(float x)
{
    uint32_t h;
    asm("cvt.rna.tf32.f32 %0, %1;" : "=r"(h) : "f"(x));
    float r = x - __uint_as_float(h);
    uint32_t l;
    asm("cvt.rna.tf32.f32 %0, %1;" : "=r"(l) : "f"(r));
    return make_uint2(h, l);
}

__device__ __forceinline__ void mma8(float d[4], const uint32_t a[4], const uint32_t b[2])
{
    asm volatile(
        "mma.sync.aligned.m16n8k8.row.col.f32.tf32.tf32.f32 "
        "{%0,%1,%2,%3}, {%4,%5,%6,%7}, {%8,%9}, {%0,%1,%2,%3};\n"
        : "+f"(d[0]), "+f"(d[1]), "+f"(d[2]), "+f"(d[3])
        : "r"(a[0]), "r"(a[1]), "r"(a[2]), "r"(a[3]), "r"(b[0]), "r"(b[1]));
}

// ---------------------------------------------------------------------------
// prep: weight transposes + BN fold
// ---------------------------------------------------------------------------
__global__ __launch_bounds__(NTHREADS) void prep_kernel(
    const float* __restrict__ W2, const float* __restrict__ W3, const float* __restrict__ W4,
    const float* __restrict__ b2, const float* __restrict__ g2, const float* __restrict__ be2,
    const float* __restrict__ m2, const float* __restrict__ v2,
    const float* __restrict__ b3, const float* __restrict__ g3, const float* __restrict__ be3,
    const float* __restrict__ m3, const float* __restrict__ v3,
    const float* __restrict__ b4, const float* __restrict__ g4, const float* __restrict__ be4,
    const float* __restrict__ m4, const float* __restrict__ v4)
{
    int idx = blockIdx.x * NTHREADS + threadIdx.x;
    if (idx < 576 * 128) {
        int k = idx >> 7, n = idx & 127;
        g_w2t[idx] = W2[n * 576 + k];
    }
    int i3 = idx - 73728;
    if (i3 >= 0 && i3 < 1152 * 256) {
        int k = i3 >> 8, n = i3 & 255;
        g_w3t[i3] = W3[n * 1152 + k];
    }
    int i4 = idx - 73728 - 294912;
    if (i4 >= 0 && i4 < 2304 * 256) {
        int k = i4 >> 8, n = i4 & 255;
        g_w4t[i4] = W4[n * 2304 + k];
    }
    if (idx < 128) {
        float s = g2[idx] * rsqrtf(v2[idx] + 1e-5f);
        g_sc2[idx] = s; g_sh2[idx] = (b2[idx] - m2[idx]) * s + be2[idx];
    } else if (idx < 384) {
        int c = idx - 128;
        float s = g3[c] * rsqrtf(v3[c] + 1e-5f);
        g_sc3[c] = s; g_sh3[c] = (b3[c] - m3[c]) * s + be3[c];
    } else if (idx < 640) {
        int c = idx - 384;
        float s = g4[c] * rsqrtf(v4[c] + 1e-5f);
        g_sc4[c] = s; g_sh4[c] = (b4[c] - m4[c]) * s + be4[c];
    }
}

// ---------------------------------------------------------------------------
// conv1: 3 -> 64, 20x20, fused BN+ReLU. One block per image. (small: FFMA ok)
// ---------------------------------------------------------------------------
__global__ __launch_bounds__(NTHREADS) void conv1_kernel(
    const float* __restrict__ x, const float* __restrict__ W,
    const float* __restrict__ bias, const float* __restrict__ gam,
    const float* __restrict__ bet, const float* __restrict__ mu,
    const float* __restrict__ var, float* __restrict__ out)
{
    __shared__ float sIn[3 * 22 * 22];
    __shared__ float sW[64 * 27];
    __shared__ float sScale[64], sShift[64];
    int b = blockIdx.x, tid = threadIdx.x;

    for (int i = tid; i < 3 * 22 * 22; i += NTHREADS) sIn[i] = 0.f;
    __syncthreads();
    const float* xb = x + (size_t)b * 1200;
    for (int i = tid; i < 1200; i += NTHREADS) {
        int ci = i / 400, p = i % 400, y = p / 20, xx = p % 20;
        sIn[ci * 484 + (y + 1) * 22 + (xx + 1)] = xb[i];
    }
    for (int i = tid; i < 1728; i += NTHREADS) sW[i] = W[i];
    if (tid < 64) {
        float sc = gam[tid] * rsqrtf(var[tid] + 1e-5f);
        sScale[tid] = sc;
        sShift[tid] = (bias[tid] - mu[tid]) * sc + bet[tid];
    }
    __syncthreads();

    int co = tid & 63, q = tid >> 6;
    float scale = sScale[co], shift = sShift[co];
    float* ob = out + ((size_t)b * 64 + co) * 400;
    for (int r = 0; r < 5; r++) {
        int y = q * 5 + r;
        float acc[20];
        #pragma unroll
        for (int xx = 0; xx < 20; xx++) acc[xx] = 0.f;
        #pragma unroll
        for (int ci = 0; ci < 3; ci++) {
            float w[9];
            #pragma unroll
            for (int k = 0; k < 9; k++) w[k] = sW[co * 27 + ci * 9 + k];
            const float* base = sIn + ci * 484 + y * 22;
            #pragma unroll
            for (int dy = 0; dy < 3; dy++) {
                const float* row = base + dy * 22;
                #pragma unroll
                for (int xx = 0; xx < 20; xx++)
                    acc[xx] += row[xx] * w[dy * 3] + row[xx + 1] * w[dy * 3 + 1]
                             + row[xx + 2] * w[dy * 3 + 2];
            }
        }
        #pragma unroll
        for (int xx = 0; xx < 20; xx++)
            ob[y * 20 + xx] = fmaxf(acc[xx] * scale + shift, 0.f);
    }
}

// ---------------------------------------------------------------------------
// maxpool 3x3 stride 2 pad 1
// ---------------------------------------------------------------------------
__global__ __launch_bounds__(NTHREADS) void pool_kernel(
    const float* __restrict__ in, float* __restrict__ out,
    int C, int H, int OH, long long total)
{
    long long idx = (long long)blockIdx.x * NTHREADS + threadIdx.x;
    if (idx >= total) return;
    int W = H, OW = OH;
    int ox = (int)(idx % OW); long long t = idx / OW;
    int oy = (int)(t % OH);  t /= OH;
    int c  = (int)(t % C);   int b = (int)(t / C);
    const float* p = in + ((size_t)b * C + c) * H * W;
    float m = -3.402823466e38f;
    #pragma unroll
    for (int dy = 0; dy < 3; dy++) {
        int iy = 2 * oy - 1 + dy;
        if (iy < 0 || iy >= H) continue;
        #pragma unroll
        for (int dx = 0; dx < 3; dx++) {
            int ix = 2 * ox - 1 + dx;
            if (ix < 0 || ix >= W) continue;
            m = fmaxf(m, p[iy * W + ix]);
        }
    }
    out[idx] = m;
}

// ---------------------------------------------------------------------------
// Tensor-core GEMM with IMPLICIT im2col on the A side.
// C[M,N] = A[M,K] x Bt[K,N], 3xTF32 (fp32-accurate).
// Tile 128x128x16, 256 threads (8 warps as 4x2), m16n8k8 fragments.
// tf32 hi/lo splits precomputed at smem-store time (uint2 planes); inner
// loop is pure LDS.64 + MMA. Global loads for chunk i+1 prefetched into
// registers before computing chunk i.
// ---------------------------------------------------------------------------
template <int EPI, int CC, int S>
__global__ __launch_bounds__(NTHREADS, 2) void gemm_tc(
    const float* __restrict__ A, const float* __restrict__ Bt,
    float* __restrict__ C, const float* __restrict__ sc,
    const float* __restrict__ sh, const float* __restrict__ bias,
    int K, int N, int ldb)
{
    __shared__ uint2 sA[16 * 136];
    __shared__ uint2 sB[16 * 136];

    int z = blockIdx.z;
    const float* Ab = A;
    const float* Bb = Bt;
    if (EPI == 3) {
        Ab += (size_t)z * 8192 * K;
        Bb += (size_t)z * 336 * 600;
    }
    int mBase = blockIdx.y * 128, nBase = blockIdx.x * 128;
    int t = threadIdx.x;
    int lane = t & 31, wid = t >> 5;
    int wm = (wid & 3) * 32, wn = (wid >> 2) * 64;
    int lc = lane & 3, lr = lane >> 2;

    // loader mapping: thread owns one tile row/col (lm) and 8 consecutive k
    int lm = t & 127;
    int lkq = (t >> 7) * 8;

    // precomputed A-row decode for implicit im2col
    int ib_off = 0, py = 0, px = 0;
    if (CC > 0) {
        const int SS = S * S;
        int r = mBase + lm;
        int b = r / SS, p = r - b * SS;
        py = p / S; px = p - py * S;
        ib_off = b * CC * SS;
    }

    float acc[2][8][4];
    #pragma unroll
    for (int mt = 0; mt < 2; mt++)
        #pragma unroll
        for (int nt = 0; nt < 8; nt++)
            #pragma unroll
            for (int e = 0; e < 4; e++) acc[mt][nt][e] = 0.f;

    float av[8], bv[8];
    int gn = nBase + lm;

    // ---- prefetch chunk 0
    {
        const int kcp = 0;
        if (CC == 0) {
            const float* base = Ab + (size_t)(mBase + lm) * K + kcp + lkq;
            float4 v0 = *(const float4*)base;
            float4 v1 = *(const float4*)(base + 4);
            av[0] = v0.x; av[1] = v0.y; av[2] = v0.z; av[3] = v0.w;
            av[4] = v1.x; av[5] = v1.y; av[6] = v1.z; av[7] = v1.w;
        } else {
            const int SS = S * S;
            const float* ib = Ab + ib_off;
            #pragma unroll
            for (int j = 0; j < 8; j++) {
                int k = kcp + lkq + j;
                int ci = k / 9, q = k - ci * 9;
                int iy = py - 1 + q / 3, ix = px - 1 + q % 3;
                float v = 0.f;
                if (iy >= 0 && iy < S && ix >= 0 && ix < S)
                    v = ib[ci * SS + iy * S + ix];
                av[j] = v;
            }
        }
        #pragma unroll
        for (int j = 0; j < 8; j++)
            bv[j] = (gn < N) ? Bb[(size_t)(kcp + lkq + j) * ldb + gn] : 0.f;
    }

    int nch = K / 16;
    for (int ch = 0; ch < nch; ch++) {
        // ---- store staged chunk (with tf32 split)
        #pragma unroll
        for (int j = 0; j < 8; j++) {
            sA[(lkq + j) * 136 + lm] = tf32split2(av[j]);
            sB[(lkq + j) * 136 + lm] = tf32split2(bv[j]);
        }
        __syncthreads();

        // ---- prefetch next chunk (clamped; redundant read of chunk 0 at end)
        {
            int kcp = (ch + 1 < nch) ? (ch + 1) * 16 : 0;
            if (CC == 0) {
                const float* base = Ab + (size_t)(mBase + lm) * K + kcp + lkq;
                float4 v0 = *(const float4*)base;
                float4 v1 = *(const float4*)(base + 4);
                av[0] = v0.x; av[1] = v0.y; av[2] = v0.z; av[3] = v0.w;
                av[4] = v1.x; av[5] = v1.y; av[6] = v1.z; av[7] = v1.w;
            } else {
                const int SS = S * S;
                const float* ib = Ab + ib_off;
                #pragma unroll
                for (int j = 0; j < 8; j++) {
                    int k = kcp + lkq + j;
                    int ci = k / 9, q = k - ci * 9;
                    int iy = py - 1 + q / 3, ix = px - 1 + q % 3;
                    float v = 0.f;
                    if (iy >= 0 && iy < S && ix >= 0 && ix < S)
                        v = ib[ci * SS + iy * S + ix];
                    av[j] = v;
                }
            }
            #pragma unroll
            for (int j = 0; j < 8; j++)
                bv[j] = (gn < N) ? Bb[(size_t)(kcp + lkq + j) * ldb + gn] : 0.f;
        }

        // ---- compute from smem (pure LDS + MMA)
        #pragma unroll
        for (int kk = 0; kk < 16; kk += 8) {
            uint32_t ah[2][4], al[2][4];
            #pragma unroll
            for (int mt = 0; mt < 2; mt++) {
                int mr = wm + mt * 16 + lr;
                uint2 f0 = sA[(kk + lc) * 136 + mr];
                uint2 f1 = sA[(kk + lc) * 136 + mr + 8];
                uint2 f2 = sA[(kk + lc + 4) * 136 + mr];
                uint2 f3 = sA[(kk + lc + 4) * 136 + mr + 8];
                ah[mt][0] = f0.x; al[mt][0] = f0.y;
                ah[mt][1] = f1.x; al[mt][1] = f1.y;
                ah[mt][2] = f2.x; al[mt][2] = f2.y;
                ah[mt][3] = f3.x; al[mt][3] = f3.y;
            }
            #pragma unroll
            for (int nt = 0; nt < 8; nt++) {
                int nc = wn + nt * 8 + lr;
                uint2 g0 = sB[(kk + lc) * 136 + nc];
                uint2 g1 = sB[(kk + lc + 4) * 136 + nc];
                uint32_t bh[2] = {g0.x, g1.x};
                uint32_t bl[2] = {g0.y, g1.y};
                #pragma unroll
                for (int mt = 0; mt < 2; mt++) {
                    mma8(acc[mt][nt], ah[mt], bh);
                    mma8(acc[mt][nt], al[mt], bh);
                    mma8(acc[mt][nt], ah[mt], bl);
                }
            }
        }
        __syncthreads();
    }

    // epilogue
    #pragma unroll
    for (int mt = 0; mt < 2; mt++) {
        #pragma unroll
        for (int nt = 0; nt < 8; nt++) {
            #pragma unroll
            for (int e = 0; e < 4; e++) {
                int row = mBase + wm + mt * 16 + lr + (e >> 1) * 8;
                int col = nBase + wn + nt * 8 + 2 * lc + (e & 1);
                float v = acc[mt][nt][e];
                if (EPI == 0) {
                    int b = row / 100, p = row - b * 100;
                    C[((size_t)b * 128 + col) * 100 + p] = fmaxf(v * sc[col] + sh[col], 0.f);
                } else if (EPI == 1) {
                    int b = row / 25, p = row - b * 25;
                    C[((size_t)b * 256 + col) * 25 + p] = fmaxf(v * sc[col] + sh[col], 0.f);
                } else if (EPI == 2) {
                    int b = row / 25, p = row - b * 25;
                    C[((size_t)p * 8192 + b) * 256 + col] = fmaxf(v * sc[col] + sh[col], 0.f);
                } else {
                    if (col < N)
                        C[((size_t)z * 8192 + row) * 600 + col] =
                            tanhf(v + bias[(size_t)z * 600 + col]);
                }
            }
        }
    }
}

// ---------------------------------------------------------------------------
// GEMM2 + softmax (600 -> 10), warp per row, Wb in smem (pad 11)
// ---------------------------------------------------------------------------
__global__ __launch_bounds__(NTHREADS) void gemm2_softmax_kernel(
    const float* __restrict__ H, const float* __restrict__ Wb,
    const float* __restrict__ bb, float* __restrict__ out)
{
    __shared__ float sW[600 * 11];
    __shared__ float sb[10];
    int n = blockIdx.y, tid = threadIdx.x;
    const float* Wn = Wb + (size_t)n * 6000;
    for (int i = tid; i < 6000; i += NTHREADS) {
        int k = i / 10, c = i % 10;
        sW[k * 11 + c] = Wn[i];
    }
    if (tid < 10) sb[tid] = bb[n * 10 + tid];
    __syncthreads();

    int warp = tid >> 5, lane = tid & 31;
    int b = blockIdx.x * 8 + warp;
    const float* hr = H + ((size_t)n * 8192 + b) * 600;
    float acc[10];
    #pragma unroll
    for (int c = 0; c < 10; c++) acc[c] = 0.f;
    for (int k = lane; k < 600; k += 32) {
        float v = hr[k];
        #pragma unroll
        for (int c = 0; c < 10; c++) acc[c] += v * sW[k * 11 + c];
    }
    #pragma unroll
    for (int c = 0; c < 10; c++) {
        #pragma unroll
        for (int off = 16; off > 0; off >>= 1)
            acc[c] += __shfl_down_sync(0xffffffffu, acc[c], off);
    }
    if (lane == 0) {
        float l[10], mx = -3.402823466e38f;
        #pragma unroll
        for (int c = 0; c < 10; c++) { l[c] = acc[c] + sb[c]; mx = fmaxf(mx, l[c]); }
        float s = 0.f;
        #pragma unroll
        for (int c = 0; c < 10; c++) { l[c] = expf(l[c] - mx); s += l[c]; }
        float inv = 1.f / s;
        float* o = out + ((size_t)n * 8192 + b) * 10;
        #pragma unroll
        for (int c = 0; c < 10; c++) o[c] = l[c] * inv;
    }
}

// ---------------------------------------------------------------------------
// neighbor gather (matches reference Brain.neighbors ordering, 5x5 grid)
// ---------------------------------------------------------------------------
__device__ __forceinline__ int nei_of(int i, int slot)
{
    int nb[8];
    #pragma unroll
    for (int t = 0; t < 8; t++) nb[t] = -1;
    int cnt = 0;
    bool l = (i % 5 != 0), r = ((i + 1) % 5 != 0), u = (i >= 5), d = (i + 5 < 25);
    if (u)      nb[cnt++] = i - 5;
    if (l)      nb[cnt++] = i - 1;
    if (r)      nb[cnt++] = i + 1;
    if (d)      nb[cnt++] = i + 5;
    if (u && l) nb[cnt++] = i - 6;
    if (u && r) nb[cnt++] = i - 4;
    if (d && l) nb[cnt++] = i + 4;
    if (d && r) nb[cnt++] = i + 6;
    return nb[slot];
}

__global__ __launch_bounds__(NTHREADS) void gather_kernel(
    const float* __restrict__ preds, const float* __restrict__ feats,
    float* __restrict__ in2)
{
    long long idx = (long long)blockIdx.x * NTHREADS + threadIdx.x;
    if (idx >= 25LL * 8192 * 336) return;
    int j = (int)(idx % 336);
    long long t = idx / 336;
    int b = (int)(t % 8192);
    int n = (int)(t / 8192);
    float v;
    if (j >= 80) {
        v = feats[((size_t)n * 8192 + b) * 256 + (j - 80)];
    } else {
        int s = j / 10, c = j % 10;
        int nei = nei_of(n, s);
        v = (nei >= 0) ? preds[((size_t)nei * 8192 + b) * 10 + c] : 0.f;
    }
    in2[idx] = v;
}

__global__ __launch_bounds__(NTHREADS) void mean_kernel(
    const float* __restrict__ second, float* __restrict__ mean)
{
    int idx = blockIdx.x * NTHREADS + threadIdx.x;
    if (idx >= 81920) return;
    float s = 0.f;
    #pragma unroll
    for (int n = 0; n < 25; n++) s += second[(size_t)n * 81920 + idx];
    mean[idx] = s * 0.04f;
}

// ---------------------------------------------------------------------------
// launch
// ---------------------------------------------------------------------------
extern "C" void kernel_launch(void* const* d_in, const int* in_sizes, int n_in,
                              void* d_out, int out_size)
{
    (void)in_sizes; (void)n_in; (void)out_size;
    float *arena = nullptr;
    float *w2t, *w3t, *w4t, *sc2, *sh2, *sc3, *sh3, *sc4, *sh4;
    cudaGetSymbolAddress((void**)&arena, g_arena);
    cudaGetSymbolAddress((void**)&w2t, g_w2t);
    cudaGetSymbolAddress((void**)&w3t, g_w3t);
    cudaGetSymbolAddress((void**)&w4t, g_w4t);
    cudaGetSymbolAddress((void**)&sc2, g_sc2);
    cudaGetSymbolAddress((void**)&sh2, g_sh2);
    cudaGetSymbolAddress((void**)&sc3, g_sc3);
    cudaGetSymbolAddress((void**)&sh3, g_sh3);
    cudaGetSymbolAddress((void**)&sc4, g_sc4);
    cudaGetSymbolAddress((void**)&sh4, g_sh4);

    const float* x   = (const float*)d_in[0];
    const float* W1  = (const float*)d_in[1];
    const float* b1  = (const float*)d_in[2];
    const float* g1  = (const float*)d_in[3];
    const float* be1 = (const float*)d_in[4];
    const float* m1  = (const float*)d_in[5];
    const float* v1  = (const float*)d_in[6];
    const float* W2  = (const float*)d_in[7];
    const float* b2  = (const float*)d_in[8];
    const float* g2  = (const float*)d_in[9];
    const float* be2 = (const float*)d_in[10];
    const float* m2  = (const float*)d_in[11];
    const float* v2  = (const float*)d_in[12];
    const float* W3  = (const float*)d_in[13];
    const float* b3  = (const float*)d_in[14];
    const float* g3  = (const float*)d_in[15];
    const float* be3 = (const float*)d_in[16];
    const float* m3  = (const float*)d_in[17];
    const float* v3  = (const float*)d_in[18];
    const float* W4  = (const float*)d_in[19];
    const float* b4  = (const float*)d_in[20];
    const float* g4  = (const float*)d_in[21];
    const float* be4 = (const float*)d_in[22];
    const float* m4  = (const float*)d_in[23];
    const float* v4  = (const float*)d_in[24];
    const float* Wa  = (const float*)d_in[25];
    const float* ba  = (const float*)d_in[26];
    const float* Wb  = (const float*)d_in[27];
    const float* bb  = (const float*)d_in[28];
    float* out = (float*)d_out;

    // prep (weight transposes + BN folds)
    prep_kernel<<<3744, NTHREADS>>>(W2, W3, W4,
        b2, g2, be2, m2, v2, b3, g3, be3, m3, v3, b4, g4, be4, m4, v4);

    // conv1 + pool1
    conv1_kernel<<<BATCH, NTHREADS>>>(x, W1, b1, g1, be1, m1, v1, arena + OFF_C1);
    {
        long long total = (long long)BATCH * 64 * 100;
        pool_kernel<<<(int)((total + NTHREADS - 1) / NTHREADS), NTHREADS>>>(
            arena + OFF_C1, arena + OFF_P1, 64, 20, 10, total);
    }
    // conv2: implicit-im2col GEMM over pool1 (K=576, N=128)
    gemm_tc<0, 64, 10><<<dim3(1, 6400, 1), NTHREADS>>>(
        arena + OFF_P1, w2t, arena + OFF_C2, sc2, sh2, nullptr, 576, 128, 128);
    // pool2
    {
        long long total = (long long)BATCH * 128 * 25;
        pool_kernel<<<(int)((total + NTHREADS - 1) / NTHREADS), NTHREADS>>>(
            arena + OFF_C2, arena + OFF_P2, 128, 10, 5, total);
    }
    // conv3: implicit-im2col GEMM over pool2 (K=1152, N=256)
    gemm_tc<1, 128, 5><<<dim3(2, 1600, 1), NTHREADS>>>(
        arena + OFF_P2, w3t, arena + OFF_C3, sc3, sh3, nullptr, 1152, 256, 256);
    // conv4: implicit-im2col GEMM over c3, writes feats[n][b][c] directly (K=2304)
    gemm_tc<2, 256, 5><<<dim3(2, 1600, 1), NTHREADS>>>(
        arena + OFF_C3, w4t, arena + OFF_FEATS, sc4, sh4, nullptr, 2304, 256, 256);
    // stage 1 MLP (first 80 inputs zero -> Wa rows 80:336, K=256)
    gemm_tc<3, 0, 0><<<dim3(5, 64, 25), NTHREADS>>>(
        arena + OFF_FEATS, Wa + 80 * 600, arena + OFF_H, nullptr, nullptr, ba,
        256, 600, 600);
    gemm2_softmax_kernel<<<dim3(1024, 25), NTHREADS>>>(arena + OFF_H, Wb, bb,
                                                       arena + OFF_PREDS);
    // neighbor gather
    {
        long long total = 25LL * 8192 * 336;
        gather_kernel<<<(int)((total + NTHREADS - 1) / NTHREADS), NTHREADS>>>(
            arena + OFF_PREDS, arena + OFF_FEATS, arena + OFF_IN2);
    }
    // stage 2 MLP (K=336)
    gemm_tc<3, 0, 0><<<dim3(5, 64, 25), NTHREADS>>>(
        arena + OFF_IN2, Wa, arena + OFF_H, nullptr, nullptr, ba,
        336, 600, 600);
    gemm2_softmax_kernel<<<dim3(1024, 25), NTHREADS>>>(arena + OFF_H, Wb, bb,
                                                       out + 81920);
    mean_kernel<<<320, NTHREADS>>>(out + 81920, out);
}

// round 6
// speedup vs baseline: 2.7106x; 1.6627x over previous
#include <cuda_runtime.h>
#include <cstdint>
#include <cstddef>

#define NTHREADS 256
#define BATCH 8192

// ---------------------------------------------------------------------------
// Scratch arena (word offsets, 4B words; lifetimes verified):
//  c1    [0, 209715200)            float   conv1 out [b][64][20][20]
//  p1    [209715200, 262144000)    split32 pool1 out [b][64][10][10]
//  c2    [0, 104857600)            float   conv2 out [b][128][10][10]
//  p2    [104857600, 131072000)    split32 pool2 out
//  c3    [131072000, 183500800)    split32 conv3 out [b][256][5][5]
//  featsH[0, 26214400) featsL[26214400, 52428800)  pair-packed [25][8192][128w]
//  H     [52428800, 175308800)     float   [25][8192][600]
//  preds [183500800, 185548800)    float   [25][8192][10]
//  in2H  [185548800, 219955200) in2L [219955200, 254361600) [25][8192][168w]
// ---------------------------------------------------------------------------
__device__ float g_arena[262144000];     // 1.049 GB

static const size_t OFF_C1      = 0;
static const size_t OFF_P1      = 209715200;
static const size_t OFF_C2      = 0;
static const size_t OFF_P2      = 104857600;
static const size_t OFF_C3      = 131072000;
static const size_t OFF_FEATS_H = 0;
static const size_t OFF_FEATS_L = 26214400;
static const size_t OFF_H       = 52428800;
static const size_t OFF_PREDS   = 183500800;
static const size_t OFF_IN2_H   = 185548800;
static const size_t OFF_IN2_L   = 219955200;

// pre-split weight planes, pair-packed along k: word(kp,n) = bf16(k=2kp+1)<<16 | bf16(k=2kp)
__device__ uint32_t g_w2h[288 * 128],  g_w2l[288 * 128];
__device__ uint32_t g_w3h[576 * 256],  g_w3l[576 * 256];
__device__ uint32_t g_w4h[1152 * 256], g_w4l[1152 * 256];
__device__ uint32_t g_wah[25 * 168 * 600], g_wal[25 * 168 * 600];
__device__ float g_sc2[128], g_sh2[128];
__device__ float g_sc3[256], g_sh3[256];
__device__ float g_sc4[256], g_sh4[256];

// ---------------------------------------------------------------------------
// bf16 helpers
// ---------------------------------------------------------------------------
__device__ __forceinline__ uint32_t f2bf(float x)
{
    unsigned short h;
    asm("cvt.rn.bf16.f32 %0, %1;" : "=h"(h) : "f"(x));
    return (uint32_t)h;
}

// element-split32: hi bf16 in high halfword, lo bf16 in low halfword
__device__ __forceinline__ uint32_t split32(float x)
{
    uint32_t hb = f2bf(x);
    float r = x - __uint_as_float(hb << 16);
    uint32_t lb = f2bf(r);
    return (hb << 16) | lb;
}

// pair-pack two floats into (h-plane word, l-plane word)
__device__ __forceinline__ void packpair(float x0, float x1, uint32_t& wh, uint32_t& wl)
{
    uint32_t s0 = split32(x0), s1 = split32(x1);
    wh = __byte_perm(s0, s1, 0x7632);   // [s0.hi16, s1.hi16]
    wl = __byte_perm(s0, s1, 0x5410);   // [s0.lo16, s1.lo16]
}

__device__ __forceinline__ void mma16(float d[4], const uint32_t a[4], const uint32_t b[2])
{
    asm volatile(
        "mma.sync.aligned.m16n8k16.row.col.f32.bf16.bf16.f32 "
        "{%0,%1,%2,%3}, {%4,%5,%6,%7}, {%8,%9}, {%0,%1,%2,%3};\n"
        : "+f"(d[0]), "+f"(d[1]), "+f"(d[2]), "+f"(d[3])
        : "r"(a[0]), "r"(a[1]), "r"(a[2]), "r"(a[3]), "r"(b[0]), "r"(b[1]));
}

// ---------------------------------------------------------------------------
// prep: split+pack weights into bf16 planes + BN folds
// ---------------------------------------------------------------------------
__global__ __launch_bounds__(NTHREADS) void prep_kernel(
    const float* __restrict__ W2, const float* __restrict__ W3,
    const float* __restrict__ W4, const float* __restrict__ Wa,
    const float* __restrict__ b2, const float* __restrict__ g2, const float* __restrict__ be2,
    const float* __restrict__ m2, const float* __restrict__ v2,
    const float* __restrict__ b3, const float* __restrict__ g3, const float* __restrict__ be3,
    const float* __restrict__ m3, const float* __restrict__ v3,
    const float* __restrict__ b4, const float* __restrict__ g4, const float* __restrict__ be4,
    const float* __restrict__ m4, const float* __restrict__ v4)
{
    int i = blockIdx.x * NTHREADS + threadIdx.x;
    if (i < 36864) {                                   // w2: [288kp][128n]
        int kp = i >> 7, n = i & 127;
        packpair(W2[n * 576 + 2 * kp], W2[n * 576 + 2 * kp + 1], g_w2h[i], g_w2l[i]);
    }
    int i3 = i - 36864;
    if (i3 >= 0 && i3 < 147456) {                      // w3: [576kp][256n]
        int kp = i3 >> 8, n = i3 & 255;
        packpair(W3[n * 1152 + 2 * kp], W3[n * 1152 + 2 * kp + 1], g_w3h[i3], g_w3l[i3]);
    }
    int i4 = i - 36864 - 147456;
    if (i4 >= 0 && i4 < 294912) {                      // w4: [1152kp][256n]
        int kp = i4 >> 8, n = i4 & 255;
        packpair(W4[n * 2304 + 2 * kp], W4[n * 2304 + 2 * kp + 1], g_w4h[i4], g_w4l[i4]);
    }
    int ia = i - 36864 - 147456 - 294912;
    if (ia >= 0 && ia < 2520000) {                     // wa: [25z][168kp][600j]
        int z = ia / 100800, r = ia % 100800;
        int kp = r / 600, j = r % 600;
        const float* w = Wa + ((size_t)z * 336 + 2 * kp) * 600 + j;
        packpair(w[0], w[600], g_wah[ia], g_wal[ia]);
    }
    int ib = i - 36864 - 147456 - 294912 - 2520000;
    if (ib >= 0 && ib < 128) {
        float s = g2[ib] * rsqrtf(v2[ib] + 1e-5f);
        g_sc2[ib] = s; g_sh2[ib] = (b2[ib] - m2[ib]) * s + be2[ib];
    } else if (ib >= 128 && ib < 384) {
        int c = ib - 128;
        float s = g3[c] * rsqrtf(v3[c] + 1e-5f);
        g_sc3[c] = s; g_sh3[c] = (b3[c] - m3[c]) * s + be3[c];
    } else if (ib >= 384 && ib < 640) {
        int c = ib - 384;
        float s = g4[c] * rsqrtf(v4[c] + 1e-5f);
        g_sc4[c] = s; g_sh4[c] = (b4[c] - m4[c]) * s + be4[c];
    }
}

// ---------------------------------------------------------------------------
// conv1: 3 -> 64, 20x20, fused BN+ReLU, float out. One block per image.
// ---------------------------------------------------------------------------
__global__ __launch_bounds__(NTHREADS) void conv1_kernel(
    const float* __restrict__ x, const float* __restrict__ W,
    const float* __restrict__ bias, const float* __restrict__ gam,
    const float* __restrict__ bet, const float* __restrict__ mu,
    const float* __restrict__ var, float* __restrict__ out)
{
    __shared__ float sIn[3 * 22 * 22];
    __shared__ float sW[64 * 27];
    __shared__ float sScale[64], sShift[64];
    int b = blockIdx.x, tid = threadIdx.x;

    for (int i = tid; i < 3 * 22 * 22; i += NTHREADS) sIn[i] = 0.f;
    __syncthreads();
    const float* xb = x + (size_t)b * 1200;
    for (int i = tid; i < 1200; i += NTHREADS) {
        int ci = i / 400, p = i % 400, y = p / 20, xx = p % 20;
        sIn[ci * 484 + (y + 1) * 22 + (xx + 1)] = xb[i];
    }
    for (int i = tid; i < 1728; i += NTHREADS) sW[i] = W[i];
    if (tid < 64) {
        float sc = gam[tid] * rsqrtf(var[tid] + 1e-5f);
        sScale[tid] = sc;
        sShift[tid] = (bias[tid] - mu[tid]) * sc + bet[tid];
    }
    __syncthreads();

    int co = tid & 63, q = tid >> 6;
    float scale = sScale[co], shift = sShift[co];
    float* ob = out + ((size_t)b * 64 + co) * 400;
    for (int r = 0; r < 5; r++) {
        int y = q * 5 + r;
        float acc[20];
        #pragma unroll
        for (int xx = 0; xx < 20; xx++) acc[xx] = 0.f;
        #pragma unroll
        for (int ci = 0; ci < 3; ci++) {
            float w[9];
            #pragma unroll
            for (int k = 0; k < 9; k++) w[k] = sW[co * 27 + ci * 9 + k];
            const float* base = sIn + ci * 484 + y * 22;
            #pragma unroll
            for (int dy = 0; dy < 3; dy++) {
                const float* row = base + dy * 22;
                #pragma unroll
                for (int xx = 0; xx < 20; xx++)
                    acc[xx] += row[xx] * w[dy * 3] + row[xx + 1] * w[dy * 3 + 1]
                             + row[xx + 2] * w[dy * 3 + 2];
            }
        }
        #pragma unroll
        for (int xx = 0; xx < 20; xx++)
            ob[y * 20 + xx] = fmaxf(acc[xx] * scale + shift, 0.f);
    }
}

// ---------------------------------------------------------------------------
// maxpool 3x3 s2 p1, float in -> element-split32 out
// ---------------------------------------------------------------------------
__global__ __launch_bounds__(NTHREADS) void pool_split_kernel(
    const float* __restrict__ in, uint32_t* __restrict__ out,
    int C, int H, int OH, long long total)
{
    long long idx = (long long)blockIdx.x * NTHREADS + threadIdx.x;
    if (idx >= total) return;
    int W = H, OW = OH;
    int ox = (int)(idx % OW); long long t = idx / OW;
    int oy = (int)(t % OH);  t /= OH;
    int c  = (int)(t % C);   int b = (int)(t / C);
    const float* p = in + ((size_t)b * C + c) * H * W;
    float m = -3.402823466e38f;
    #pragma unroll
    for (int dy = 0; dy < 3; dy++) {
        int iy = 2 * oy - 1 + dy;
        if (iy < 0 || iy >= H) continue;
        #pragma unroll
        for (int dx = 0; dx < 3; dx++) {
            int ix = 2 * ox - 1 + dx;
            if (ix < 0 || ix >= W) continue;
            m = fmaxf(m, p[iy * W + ix]);
        }
    }
    out[idx] = split32(m);
}

// ---------------------------------------------------------------------------
// bf16 tensor-core GEMM, exact (Ah+Al)(Bh+Bl) 4-product scheme.
// Tile 128x128x16, 8 warps (4x2), m16n8k16. All operands pre-split:
//  CC>0 : A = element-split32 activations, implicit im2col
//  CC==0: A/A2 = pair-packed h/l planes (MLP), aw = words per row
//  Bh/Bl: pair-packed weight planes [K/2][ldb]
// EPI: 0 float [b][128][100]; 1 split32 [b][256][25];
//      2 pair-packed feats h/l [n][b][128w]; 3 float tanh H[z][8192][600]
// ---------------------------------------------------------------------------
#define GEMM_FETCH(kc_)                                                          \
    {                                                                            \
        int kc__ = (kc_);                                                        \
        if (CC == 0) {                                                           \
            uint4 h4 = *(const uint4*)(Abh + (size_t)(mBase + lm) * aw           \
                                       + (kc__ >> 1) + (lkq >> 1));              \
            uint4 l4 = *(const uint4*)(Abl + (size_t)(mBase + lm) * aw           \
                                       + (kc__ >> 1) + (lkq >> 1));              \
            avh[0] = h4.x; avh[1] = h4.y; avh[2] = h4.z; avh[3] = h4.w;          \
            avl[0] = l4.x; avl[1] = l4.y; avl[2] = l4.z; avl[3] = l4.w;          \
        } else {                                                                 \
            uint32_t e[8];                                                       \
            _Pragma("unroll")                                                    \
            for (int j = 0; j < 8; j++) {                                        \
                int k = kc__ + lkq + j;                                          \
                int ci = k / 9, q = k - ci * 9;                                  \
                int iy = py - 1 + q / 3, ix = px - 1 + q % 3;                    \
                uint32_t v = 0u;                                                 \
                if (iy >= 0 && iy < S && ix >= 0 && ix < S)                      \
                    v = A[ib_off + ci * S * S + iy * S + ix];                    \
                e[j] = v;                                                        \
            }                                                                    \
            _Pragma("unroll")                                                    \
            for (int tt = 0; tt < 4; tt++) {                                     \
                avh[tt] = __byte_perm(e[2 * tt], e[2 * tt + 1], 0x7632);         \
                avl[tt] = __byte_perm(e[2 * tt], e[2 * tt + 1], 0x5410);         \
            }                                                                    \
        }                                                                        \
        _Pragma("unroll")                                                        \
        for (int jj = 0; jj < 4; jj++) {                                         \
            int kp = (kc__ >> 1) + (lkq >> 1) + jj;                              \
            bvh[jj] = (gn < N) ? Bbh[(size_t)kp * ldb + gn] : 0u;                \
            bvl[jj] = (gn < N) ? Bbl[(size_t)kp * ldb + gn] : 0u;                \
        }                                                                        \
    }

template <int EPI, int CC, int S>
__global__ __launch_bounds__(NTHREADS, 2) void gemm_bf16(
    const uint32_t* __restrict__ A, const uint32_t* __restrict__ A2,
    const uint32_t* __restrict__ Bh, const uint32_t* __restrict__ Bl,
    void* __restrict__ Cv, void* __restrict__ C2v,
    const float* __restrict__ sc, const float* __restrict__ sh,
    const float* __restrict__ bias,
    int K, int N, int ldb, int aw, int bStrideZ, int kpOff)
{
    __shared__ uint32_t sAh[128 * 12], sAl[128 * 12];
    __shared__ uint32_t sBh[128 * 12], sBl[128 * 12];

    int z = blockIdx.z;
    const uint32_t* Abh = A;
    const uint32_t* Abl = A2;
    const uint32_t* Bbh = Bh + (size_t)kpOff * ldb;
    const uint32_t* Bbl = Bl + (size_t)kpOff * ldb;
    if (EPI == 3) {
        Abh += (size_t)z * 8192 * aw;
        Abl += (size_t)z * 8192 * aw;
        Bbh += (size_t)z * bStrideZ;
        Bbl += (size_t)z * bStrideZ;
    }
    int mBase = blockIdx.y * 128, nBase = blockIdx.x * 128;
    int t = threadIdx.x, lane = t & 31, wid = t >> 5;
    int wm = (wid & 3) * 32, wn = (wid >> 2) * 64;
    int lc = lane & 3, lr = lane >> 2;

    int lm = t & 127, lkq = (t >> 7) * 8;
    int gn = nBase + lm;

    int ib_off = 0, py = 0, px = 0;
    if (CC > 0) {
        const int SS = S * S;
        int r = mBase + lm;
        int b = r / SS, p = r - b * SS;
        py = p / S; px = p - py * S;
        ib_off = b * CC * SS;
    }

    float acc[2][8][4];
    #pragma unroll
    for (int mt = 0; mt < 2; mt++)
        #pragma unroll
        for (int nt = 0; nt < 8; nt++)
            #pragma unroll
            for (int e = 0; e < 4; e++) acc[mt][nt][e] = 0.f;

    uint32_t avh[4], avl[4], bvh[4], bvl[4];
    GEMM_FETCH(0);

    int nch = K / 16;
    for (int ch = 0; ch < nch; ch++) {
        *(uint4*)&sAh[lm * 12 + (lkq >> 1)] = make_uint4(avh[0], avh[1], avh[2], avh[3]);
        *(uint4*)&sAl[lm * 12 + (lkq >> 1)] = make_uint4(avl[0], avl[1], avl[2], avl[3]);
        *(uint4*)&sBh[lm * 12 + (lkq >> 1)] = make_uint4(bvh[0], bvh[1], bvh[2], bvh[3]);
        *(uint4*)&sBl[lm * 12 + (lkq >> 1)] = make_uint4(bvl[0], bvl[1], bvl[2], bvl[3]);
        __syncthreads();

        int kcn = (ch + 1 < nch) ? (ch + 1) * 16 : 0;
        GEMM_FETCH(kcn);

        uint32_t fah[2][4], fal[2][4];
        #pragma unroll
        for (int mt = 0; mt < 2; mt++) {
            int mr = wm + mt * 16 + lr;
            fah[mt][0] = sAh[mr * 12 + lc];
            fah[mt][1] = sAh[(mr + 8) * 12 + lc];
            fah[mt][2] = sAh[mr * 12 + lc + 4];
            fah[mt][3] = sAh[(mr + 8) * 12 + lc + 4];
            fal[mt][0] = sAl[mr * 12 + lc];
            fal[mt][1] = sAl[(mr + 8) * 12 + lc];
            fal[mt][2] = sAl[mr * 12 + lc + 4];
            fal[mt][3] = sAl[(mr + 8) * 12 + lc + 4];
        }
        #pragma unroll
        for (int nt = 0; nt < 8; nt++) {
            int nc = wn + nt * 8 + lr;
            uint32_t bhf[2] = { sBh[nc * 12 + lc], sBh[nc * 12 + lc + 4] };
            uint32_t blf[2] = { sBl[nc * 12 + lc], sBl[nc * 12 + lc + 4] };
            #pragma unroll
            for (int mt = 0; mt < 2; mt++) {
                mma16(acc[mt][nt], fah[mt], bhf);
                mma16(acc[mt][nt], fal[mt], bhf);
                mma16(acc[mt][nt], fah[mt], blf);
                mma16(acc[mt][nt], fal[mt], blf);
            }
        }
        __syncthreads();
    }

    // epilogue
    #pragma unroll
    for (int mt = 0; mt < 2; mt++) {
        #pragma unroll
        for (int nt = 0; nt < 8; nt++) {
            if (EPI == 2) {
                #pragma unroll
                for (int rr = 0; rr < 2; rr++) {
                    int row = mBase + wm + mt * 16 + lr + rr * 8;
                    int col = nBase + wn + nt * 8 + 2 * lc;
                    float v0 = acc[mt][nt][rr * 2 + 0];
                    float v1 = acc[mt][nt][rr * 2 + 1];
                    v0 = fmaxf(v0 * sc[col] + sh[col], 0.f);
                    v1 = fmaxf(v1 * sc[col + 1] + sh[col + 1], 0.f);
                    int b = row / 25, p = row - b * 25;
                    uint32_t wh, wl;
                    packpair(v0, v1, wh, wl);
                    size_t o = ((size_t)p * 8192 + b) * 128 + (col >> 1);
                    ((uint32_t*)Cv)[o]  = wh;
                    ((uint32_t*)C2v)[o] = wl;
                }
            } else {
                #pragma unroll
                for (int e = 0; e < 4; e++) {
                    int row = mBase + wm + mt * 16 + lr + (e >> 1) * 8;
                    int col = nBase + wn + nt * 8 + 2 * lc + (e & 1);
                    float v = acc[mt][nt][e];
                    if (EPI == 0) {
                        int b = row / 100, p = row - b * 100;
                        ((float*)Cv)[((size_t)b * 128 + col) * 100 + p] =
                            fmaxf(v * sc[col] + sh[col], 0.f);
                    } else if (EPI == 1) {
                        int b = row / 25, p = row - b * 25;
                        ((uint32_t*)Cv)[((size_t)b * 256 + col) * 25 + p] =
                            split32(fmaxf(v * sc[col] + sh[col], 0.f));
                    } else {
                        if (col < N)
                            ((float*)Cv)[((size_t)z * 8192 + row) * 600 + col] =
                                tanhf(v + bias[(size_t)z * 600 + col]);
                    }
                }
            }
        }
    }
}

// ---------------------------------------------------------------------------
// GEMM2 + softmax (600 -> 10), warp per row, Wb in smem (pad 11)
// ---------------------------------------------------------------------------
__global__ __launch_bounds__(NTHREADS) void gemm2_softmax_kernel(
    const float* __restrict__ H, const float* __restrict__ Wb,
    const float* __restrict__ bb, float* __restrict__ out)
{
    __shared__ float sW[600 * 11];
    __shared__ float sb[10];
    int n = blockIdx.y, tid = threadIdx.x;
    const float* Wn = Wb + (size_t)n * 6000;
    for (int i = tid; i < 6000; i += NTHREADS) {
        int k = i / 10, c = i % 10;
        sW[k * 11 + c] = Wn[i];
    }
    if (tid < 10) sb[tid] = bb[n * 10 + tid];
    __syncthreads();

    int warp = tid >> 5, lane = tid & 31;
    int b = blockIdx.x * 8 + warp;
    const float* hr = H + ((size_t)n * 8192 + b) * 600;
    float acc[10];
    #pragma unroll
    for (int c = 0; c < 10; c++) acc[c] = 0.f;
    for (int k = lane; k < 600; k += 32) {
        float v = hr[k];
        #pragma unroll
        for (int c = 0; c < 10; c++) acc[c] += v * sW[k * 11 + c];
    }
    #pragma unroll
    for (int c = 0; c < 10; c++) {
        #pragma unroll
        for (int off = 16; off > 0; off >>= 1)
            acc[c] += __shfl_down_sync(0xffffffffu, acc[c], off);
    }
    if (lane == 0) {
        float l[10], mx = -3.402823466e38f;
        #pragma unroll
        for (int c = 0; c < 10; c++) { l[c] = acc[c] + sb[c]; mx = fmaxf(mx, l[c]); }
        float s = 0.f;
        #pragma unroll
        for (int c = 0; c < 10; c++) { l[c] = expf(l[c] - mx); s += l[c]; }
        float inv = 1.f / s;
        float* o = out + ((size_t)n * 8192 + b) * 10;
        #pragma unroll
        for (int c = 0; c < 10; c++) o[c] = l[c] * inv;
    }
}

// ---------------------------------------------------------------------------
// neighbor gather -> pair-packed in2 planes
// ---------------------------------------------------------------------------
__device__ __forceinline__ int nei_of(int i, int slot)
{
    int nb[8];
    #pragma unroll
    for (int t = 0; t < 8; t++) nb[t] = -1;
    int cnt = 0;
    bool l = (i % 5 != 0), r = ((i + 1) % 5 != 0), u = (i >= 5), d = (i + 5 < 25);
    if (u)      nb[cnt++] = i - 5;
    if (l)      nb[cnt++] = i - 1;
    if (r)      nb[cnt++] = i + 1;
    if (d)      nb[cnt++] = i + 5;
    if (u && l) nb[cnt++] = i - 6;
    if (u && r) nb[cnt++] = i - 4;
    if (d && l) nb[cnt++] = i + 4;
    if (d && r) nb[cnt++] = i + 6;
    return nb[slot];
}

__global__ __launch_bounds__(NTHREADS) void gather_kernel(
    const float* __restrict__ preds,
    const uint32_t* __restrict__ fh, const uint32_t* __restrict__ fl,
    uint32_t* __restrict__ ih, uint32_t* __restrict__ il)
{
    long long idx = (long long)blockIdx.x * NTHREADS + threadIdx.x;
    if (idx >= 25LL * 8192 * 168) return;
    int j = (int)(idx % 168);
    long long t = idx / 168;
    int b = (int)(t % 8192);
    int n = (int)(t / 8192);
    uint32_t wh, wl;
    if (j >= 40) {
        size_t src = ((size_t)n * 8192 + b) * 128 + (j - 40);
        wh = fh[src]; wl = fl[src];
    } else {
        int c0 = (2 * j) % 10, s = (2 * j) / 10;
        int nei = nei_of(n, s);
        float p0 = 0.f, p1 = 0.f;
        if (nei >= 0) {
            const float* pp = preds + ((size_t)nei * 8192 + b) * 10 + c0;
            p0 = pp[0]; p1 = pp[1];
        }
        packpair(p0, p1, wh, wl);
    }
    ih[idx] = wh;
    il[idx] = wl;
}

__global__ __launch_bounds__(NTHREADS) void mean_kernel(
    const float* __restrict__ second, float* __restrict__ mean)
{
    int idx = blockIdx.x * NTHREADS + threadIdx.x;
    if (idx >= 81920) return;
    float s = 0.f;
    #pragma unroll
    for (int n = 0; n < 25; n++) s += second[(size_t)n * 81920 + idx];
    mean[idx] = s * 0.04f;
}

// ---------------------------------------------------------------------------
// launch
// ---------------------------------------------------------------------------
extern "C" void kernel_launch(void* const* d_in, const int* in_sizes, int n_in,
                              void* d_out, int out_size)
{
    (void)in_sizes; (void)n_in; (void)out_size;
    float* arena = nullptr;
    uint32_t *w2h, *w2l, *w3h, *w3l, *w4h, *w4l, *wah, *wal;
    float *sc2, *sh2, *sc3, *sh3, *sc4, *sh4;
    cudaGetSymbolAddress((void**)&arena, g_arena);
    cudaGetSymbolAddress((void**)&w2h, g_w2h);  cudaGetSymbolAddress((void**)&w2l, g_w2l);
    cudaGetSymbolAddress((void**)&w3h, g_w3h);  cudaGetSymbolAddress((void**)&w3l, g_w3l);
    cudaGetSymbolAddress((void**)&w4h, g_w4h);  cudaGetSymbolAddress((void**)&w4l, g_w4l);
    cudaGetSymbolAddress((void**)&wah, g_wah);  cudaGetSymbolAddress((void**)&wal, g_wal);
    cudaGetSymbolAddress((void**)&sc2, g_sc2);  cudaGetSymbolAddress((void**)&sh2, g_sh2);
    cudaGetSymbolAddress((void**)&sc3, g_sc3);  cudaGetSymbolAddress((void**)&sh3, g_sh3);
    cudaGetSymbolAddress((void**)&sc4, g_sc4);  cudaGetSymbolAddress((void**)&sh4, g_sh4);
    uint32_t* arenau = (uint32_t*)arena;

    const float* x   = (const float*)d_in[0];
    const float* W1  = (const float*)d_in[1];
    const float* b1  = (const float*)d_in[2];
    const float* g1  = (const float*)d_in[3];
    const float* be1 = (const float*)d_in[4];
    const float* m1  = (const float*)d_in[5];
    const float* v1  = (const float*)d_in[6];
    const float* W2  = (const float*)d_in[7];
    const float* b2  = (const float*)d_in[8];
    const float* g2  = (const float*)d_in[9];
    const float* be2 = (const float*)d_in[10];
    const float* m2  = (const float*)d_in[11];
    const float* v2  = (const float*)d_in[12];
    const float* W3  = (const float*)d_in[13];
    const float* b3  = (const float*)d_in[14];
    const float* g3  = (const float*)d_in[15];
    const float* be3 = (const float*)d_in[16];
    const float* m3  = (const float*)d_in[17];
    const float* v3  = (const float*)d_in[18];
    const float* W4  = (const float*)d_in[19];
    const float* b4  = (const float*)d_in[20];
    const float* g4  = (const float*)d_in[21];
    const float* be4 = (const float*)d_in[22];
    const float* m4  = (const float*)d_in[23];
    const float* v4  = (const float*)d_in[24];
    const float* Wa  = (const float*)d_in[25];
    const float* ba  = (const float*)d_in[26];
    const float* Wb  = (const float*)d_in[27];
    const float* bb  = (const float*)d_in[28];
    float* out = (float*)d_out;

    // prep: weight splits + BN folds (2,999,872 work items)
    prep_kernel<<<11719, NTHREADS>>>(W2, W3, W4, Wa,
        b2, g2, be2, m2, v2, b3, g3, be3, m3, v3, b4, g4, be4, m4, v4);

    // conv1 (float) + pool1 (split32)
    conv1_kernel<<<BATCH, NTHREADS>>>(x, W1, b1, g1, be1, m1, v1, arena + OFF_C1);
    {
        long long total = (long long)BATCH * 64 * 100;
        pool_split_kernel<<<(int)((total + NTHREADS - 1) / NTHREADS), NTHREADS>>>(
            arena + OFF_C1, arenau + OFF_P1, 64, 20, 10, total);
    }
    // conv2: implicit-im2col bf16 GEMM (K=576, N=128) -> float c2
    gemm_bf16<0, 64, 10><<<dim3(1, 6400, 1), NTHREADS>>>(
        arenau + OFF_P1, nullptr, w2h, w2l, arena + OFF_C2, nullptr,
        sc2, sh2, nullptr, 576, 128, 128, 0, 0, 0);
    // pool2 (split32)
    {
        long long total = (long long)BATCH * 128 * 25;
        pool_split_kernel<<<(int)((total + NTHREADS - 1) / NTHREADS), NTHREADS>>>(
            arena + OFF_C2, arenau + OFF_P2, 128, 10, 5, total);
    }
    // conv3 (K=1152, N=256) -> split32 c3
    gemm_bf16<1, 128, 5><<<dim3(2, 1600, 1), NTHREADS>>>(
        arenau + OFF_P2, nullptr, w3h, w3l, arenau + OFF_C3, nullptr,
        sc3, sh3, nullptr, 1152, 256, 256, 0, 0, 0);
    // conv4 (K=2304, N=256) -> pair-packed feats h/l
    gemm_bf16<2, 256, 5><<<dim3(2, 1600, 1), NTHREADS>>>(
        arenau + OFF_C3, nullptr, w4h, w4l,
        arenau + OFF_FEATS_H, arenau + OFF_FEATS_L,
        sc4, sh4, nullptr, 2304, 256, 256, 0, 0, 0);
    // stage 1 MLP (K=256, Wa rows 80:336 -> kpOff=40) -> float H
    gemm_bf16<3, 0, 0><<<dim3(5, 64, 25), NTHREADS>>>(
        arenau + OFF_FEATS_H, arenau + OFF_FEATS_L, wah, wal,
        arena + OFF_H, nullptr, nullptr, nullptr, ba,
        256, 600, 600, 128, 100800, 40);
    gemm2_softmax_kernel<<<dim3(1024, 25), NTHREADS>>>(arena + OFF_H, Wb, bb,
                                                       arena + OFF_PREDS);
    // gather -> pair-packed in2 h/l
    {
        long long total = 25LL * 8192 * 168;
        gather_kernel<<<(int)((total + NTHREADS - 1) / NTHREADS), NTHREADS>>>(
            arena + OFF_PREDS, arenau + OFF_FEATS_H, arenau + OFF_FEATS_L,
            arenau + OFF_IN2_H, arenau + OFF_IN2_L);
    }
    // stage 2 MLP (K=336)
    gemm_bf16<3, 0, 0><<<dim3(5, 64, 25), NTHREADS>>>(
        arenau + OFF_IN2_H, arenau + OFF_IN2_L, wah, wal,
        arena + OFF_H, nullptr, nullptr, nullptr, ba,
        336, 600, 600, 168, 100800, 0);
    gemm2_softmax_kernel<<<dim3(1024, 25), NTHREADS>>>(arena + OFF_H, Wb, bb,
                                                       out + 81920);
    mean_kernel<<<320, NTHREADS>>>(out + 81920, out);
}